// round 2
// baseline (speedup 1.0000x reference)
#include <cuda_runtime.h>
#include <math.h>

#define NN   20000
#define EE   320000
#define ETOT (EE + NN)
#define FEAT 64
#define HID  128
#define OUTD 10
#define KIN  (HID + FEAT)   // 192

// ---------------- scratch (static device memory; no allocations) ----------------
__device__ float g_comb[NN * KIN];
__device__ float g_x0  [NN * HID];
__device__ float g_xl1 [NN * 512];
__device__ float g_xr1 [NN * 512];
__device__ float g_x1  [NN * 512];
__device__ float g_xl2 [NN * HID];
__device__ float g_xr2 [NN * HID];
__device__ float g_x2  [NN * HID];
__device__ int   g_deg [NN];
__device__ int   g_rowptr[NN + 1];
__device__ int   g_cnt [NN];
__device__ int   g_csr [ETOT];

// ---------------- small utility kernels ----------------
__global__ void k_zero_int(int* p, int n) {
    int i = blockIdx.x * blockDim.x + threadIdx.x;
    if (i < n) p[i] = 0;
}

// histogram of dst (including self loops appended at the end)
__global__ void k_hist(const int* __restrict__ ei, int* __restrict__ deg) {
    int i = blockIdx.x * blockDim.x + threadIdx.x;
    if (i >= ETOT) return;
    int d = (i < EE) ? ei[EE + i] : (i - EE);
    atomicAdd(&deg[d], 1);
}

// exclusive scan of deg -> rowptr, single block of 512 threads
__global__ void k_scan(const int* __restrict__ deg, int* __restrict__ rowptr) {
    __shared__ int sh[512];
    const int VPT = (NN + 511) / 512;   // 40
    int t = threadIdx.x;
    int base = t * VPT;
    int sum = 0;
    for (int j = 0; j < VPT; j++) {
        int i = base + j;
        if (i < NN) sum += deg[i];
    }
    sh[t] = sum;
    __syncthreads();
    for (int off = 1; off < 512; off <<= 1) {
        int v = (t >= off) ? sh[t - off] : 0;
        __syncthreads();
        sh[t] += v;
        __syncthreads();
    }
    int run = (t == 0) ? 0 : sh[t - 1];
    for (int j = 0; j < VPT; j++) {
        int i = base + j;
        if (i < NN) { rowptr[i] = run; run += deg[i]; }
    }
    if (t == 511) rowptr[NN] = sh[511];
}

__global__ void k_scatter(const int* __restrict__ ei, const int* __restrict__ rowptr,
                          int* __restrict__ cnt, int* __restrict__ csr) {
    int i = blockIdx.x * blockDim.x + threadIdx.x;
    if (i >= ETOT) return;
    int s, d;
    if (i < EE) { s = ei[i]; d = ei[EE + i]; }
    else        { s = d = i - EE; }
    int p = rowptr[d] + atomicAdd(&cnt[d], 1);
    csr[p] = s;
}

// combined = [emb[ids], feats]
__global__ void k_combined(const float* __restrict__ xp, const float* __restrict__ emb,
                           float* __restrict__ comb) {
    int idx = blockIdx.x * blockDim.x + threadIdx.x;
    if (idx >= NN * KIN) return;
    int i = idx / KIN;
    int k = idx - i * KIN;
    float v;
    if (k < HID) {
        int id = (int)xp[i * (FEAT + 1)];
        v = emb[id * HID + k];
    } else {
        v = xp[i * (FEAT + 1) + 1 + (k - HID)];
    }
    comb[idx] = v;
}

// ---------------- GEMM: 128x128 tile, BK=8, 256 threads, 8x8 per thread ----------------
__global__ void __launch_bounds__(256) k_gemm128(
    const float* __restrict__ A, const float* __restrict__ B, float* __restrict__ C,
    int M, int Ncol, int K) {
    __shared__ float As[8][128];
    __shared__ float Bs[8][128];
    int tid = threadIdx.x;
    int brow = blockIdx.y * 128, bcol = blockIdx.x * 128;
    int arow = tid >> 1, akoff = (tid & 1) * 4;
    int bkrow = tid >> 5, bcoff = (tid & 31) << 2;
    int tx = tid & 15, ty = tid >> 4;
    float acc[8][8];
#pragma unroll
    for (int i = 0; i < 8; i++)
#pragma unroll
        for (int j = 0; j < 8; j++) acc[i][j] = 0.f;
    bool aok = (brow + arow) < M;
    for (int k0 = 0; k0 < K; k0 += 8) {
        float4 av = aok ? *(const float4*)(A + (size_t)(brow + arow) * K + k0 + akoff)
                        : make_float4(0.f, 0.f, 0.f, 0.f);
        As[akoff + 0][arow] = av.x;
        As[akoff + 1][arow] = av.y;
        As[akoff + 2][arow] = av.z;
        As[akoff + 3][arow] = av.w;
        *(float4*)&Bs[bkrow][bcoff] =
            *(const float4*)(B + (size_t)(k0 + bkrow) * Ncol + bcol + bcoff);
        __syncthreads();
#pragma unroll
        for (int k = 0; k < 8; k++) {
            float a[8], b[8];
            *(float4*)(a)     = *(float4*)&As[k][ty * 8];
            *(float4*)(a + 4) = *(float4*)&As[k][ty * 8 + 4];
            *(float4*)(b)     = *(float4*)&Bs[k][tx * 8];
            *(float4*)(b + 4) = *(float4*)&Bs[k][tx * 8 + 4];
#pragma unroll
            for (int i = 0; i < 8; i++)
#pragma unroll
                for (int j = 0; j < 8; j++) acc[i][j] += a[i] * b[j];
        }
        __syncthreads();
    }
#pragma unroll
    for (int i = 0; i < 8; i++) {
        int r = brow + ty * 8 + i;
        if (r < M) {
#pragma unroll
            for (int j = 0; j < 8; j += 4) {
                float4 v = make_float4(acc[i][j], acc[i][j + 1], acc[i][j + 2], acc[i][j + 3]);
                *(float4*)(C + (size_t)r * Ncol + bcol + tx * 8 + j) = v;
            }
        }
    }
}

// ---------------- GEMM: 64x128 tile, BK=16, 256 threads, 4x8 per thread (+bias/relu) ----
__global__ void __launch_bounds__(256) k_gemm64(
    const float* __restrict__ A, const float* __restrict__ B,
    const float* __restrict__ bias, float* __restrict__ C,
    int M, int Ncol, int K, int relu) {
    __shared__ float As[16][64];
    __shared__ float Bs[16][128];
    int tid = threadIdx.x;
    int brow = blockIdx.y * 64, bcol = blockIdx.x * 128;
    int arow = tid >> 2, akoff = (tid & 3) * 4;
    int bcoff = (tid & 31) << 2;
    int tx = tid & 15, ty = tid >> 4;
    float acc[4][8];
#pragma unroll
    for (int i = 0; i < 4; i++)
#pragma unroll
        for (int j = 0; j < 8; j++) acc[i][j] = 0.f;
    bool aok = (brow + arow) < M;
    for (int k0 = 0; k0 < K; k0 += 16) {
        float4 av = aok ? *(const float4*)(A + (size_t)(brow + arow) * K + k0 + akoff)
                        : make_float4(0.f, 0.f, 0.f, 0.f);
        As[akoff + 0][arow] = av.x;
        As[akoff + 1][arow] = av.y;
        As[akoff + 2][arow] = av.z;
        As[akoff + 3][arow] = av.w;
#pragma unroll
        for (int it = 0; it < 2; it++) {
            int kr = (tid >> 5) + it * 8;
            *(float4*)&Bs[kr][bcoff] =
                *(const float4*)(B + (size_t)(k0 + kr) * Ncol + bcol + bcoff);
        }
        __syncthreads();
#pragma unroll
        for (int k = 0; k < 16; k++) {
            float a[4], b[8];
            *(float4*)(a)     = *(float4*)&As[k][ty * 4];
            *(float4*)(b)     = *(float4*)&Bs[k][tx * 8];
            *(float4*)(b + 4) = *(float4*)&Bs[k][tx * 8 + 4];
#pragma unroll
            for (int i = 0; i < 4; i++)
#pragma unroll
                for (int j = 0; j < 8; j++) acc[i][j] += a[i] * b[j];
        }
        __syncthreads();
    }
#pragma unroll
    for (int i = 0; i < 4; i++) {
        int r = brow + ty * 4 + i;
        if (r < M) {
#pragma unroll
            for (int j = 0; j < 8; j++) {
                int c = bcol + tx * 8 + j;
                float v = acc[i][j];
                if (bias) v += bias[c];
                if (relu) v = fmaxf(v, 0.f);
                C[(size_t)r * Ncol + c] = v;
            }
        }
    }
}

// ---------------- GATv2 per-dst-node kernel: online softmax, single edge pass ----------
template <int HEADS, bool RELU>
__global__ void __launch_bounds__(128) k_gat(
    const float* __restrict__ xl, const float* __restrict__ xr,
    const float* __restrict__ att, const float* __restrict__ bias,
    const int* __restrict__ rowptr, const int* __restrict__ csr,
    float* __restrict__ out) {
    int node = blockIdx.x;
    int t = threadIdx.x;
    int lane = t & 31, warp = t >> 5;
    __shared__ float xr_sh[HEADS * 128];
    __shared__ float att_sh[HEADS * 128];
    __shared__ float red[4 * HEADS];
    __shared__ float bcast[HEADS];
#pragma unroll
    for (int h = 0; h < HEADS; h++) {
        xr_sh[h * 128 + t]  = xr[(size_t)node * HEADS * 128 + h * 128 + t];
        att_sh[h * 128 + t] = att[h * 128 + t];
    }
    __syncthreads();
    float m[HEADS], s[HEADS], acc[HEADS];
#pragma unroll
    for (int h = 0; h < HEADS; h++) { m[h] = -INFINITY; s[h] = 0.f; acc[h] = 0.f; }
    int beg = rowptr[node], end = rowptr[node + 1];
    for (int i = beg; i < end; i++) {
        int src = csr[i];
        const float* xlp = xl + (size_t)src * HEADS * 128;
        float xlv[HEADS], p[HEADS];
#pragma unroll
        for (int h = 0; h < HEADS; h++) {
            xlv[h] = xlp[h * 128 + t];
            float v = xlv[h] + xr_sh[h * 128 + t];
            v = (v > 0.f) ? v : 0.2f * v;
            p[h] = v * att_sh[h * 128 + t];
        }
#pragma unroll
        for (int h = 0; h < HEADS; h++)
#pragma unroll
            for (int off = 16; off > 0; off >>= 1)
                p[h] += __shfl_down_sync(0xffffffffu, p[h], off);
        if (lane == 0) {
#pragma unroll
            for (int h = 0; h < HEADS; h++) red[warp * HEADS + h] = p[h];
        }
        __syncthreads();
        if (t < HEADS)
            bcast[t] = red[t] + red[HEADS + t] + red[2 * HEADS + t] + red[3 * HEADS + t];
        __syncthreads();
#pragma unroll
        for (int h = 0; h < HEADS; h++) {
            float e = bcast[h];
            float mn = fmaxf(m[h], e);
            float cs = __expf(m[h] - mn);   // 0 when m==-inf
            float w  = __expf(e - mn);
            s[h]   = s[h] * cs + w;
            acc[h] = acc[h] * cs + w * xlv[h];
            m[h]   = mn;
        }
        __syncthreads();
    }
#pragma unroll
    for (int h = 0; h < HEADS; h++) {
        float o = acc[h] / (s[h] + 1e-16f) + bias[h * 128 + t];
        if (RELU) o = fmaxf(o, 0.f);
        out[(size_t)node * HEADS * 128 + h * 128 + t] = o;
    }
}

// ---------------- output GEMM: [N,128] @ [128,10] + b ----------------
__global__ void __launch_bounds__(256) k_out(const float* __restrict__ x2,
                                             const float* __restrict__ W,
                                             const float* __restrict__ b,
                                             float* __restrict__ out) {
    int warp = threadIdx.x >> 5, lane = threadIdx.x & 31;
    int node = blockIdx.x * 8 + warp;
    if (node >= NN) return;
    float4 xv = *(const float4*)(x2 + (size_t)node * HID + lane * 4);
    float a[4] = {xv.x, xv.y, xv.z, xv.w};
    float acc[OUTD];
#pragma unroll
    for (int j = 0; j < OUTD; j++) acc[j] = 0.f;
#pragma unroll
    for (int q = 0; q < 4; q++) {
        int k = lane * 4 + q;
        float x = a[q];
#pragma unroll
        for (int j = 0; j < OUTD; j++) acc[j] += x * W[k * OUTD + j];
    }
#pragma unroll
    for (int j = 0; j < OUTD; j++)
#pragma unroll
        for (int off = 16; off > 0; off >>= 1)
            acc[j] += __shfl_down_sync(0xffffffffu, acc[j], off);
    if (lane == 0) {
#pragma unroll
        for (int j = 0; j < OUTD; j++) out[(size_t)node * OUTD + j] = acc[j] + b[j];
    }
}

// ---------------- launcher ----------------
extern "C" void kernel_launch(void* const* d_in, const int* in_sizes, int n_in,
                              void* d_out, int out_size) {
    const float* xp     = (const float*)d_in[0];
    const int*   ei     = (const int*)  d_in[1];
    const float* emb    = (const float*)d_in[2];
    const float* proj_W = (const float*)d_in[3];
    const float* proj_b = (const float*)d_in[4];
    const float* W1l    = (const float*)d_in[5];
    const float* W1r    = (const float*)d_in[6];
    const float* att1   = (const float*)d_in[7];
    const float* b1     = (const float*)d_in[8];
    const float* W2l    = (const float*)d_in[9];
    const float* W2r    = (const float*)d_in[10];
    const float* att2   = (const float*)d_in[11];
    const float* b2     = (const float*)d_in[12];
    const float* out_W  = (const float*)d_in[13];
    const float* out_b  = (const float*)d_in[14];
    float* out = (float*)d_out;

    float *comb, *x0, *xl1, *xr1, *x1, *xl2, *xr2, *x2;
    int *deg, *rowptr, *cnt, *csr;
    cudaGetSymbolAddress((void**)&comb,   g_comb);
    cudaGetSymbolAddress((void**)&x0,     g_x0);
    cudaGetSymbolAddress((void**)&xl1,    g_xl1);
    cudaGetSymbolAddress((void**)&xr1,    g_xr1);
    cudaGetSymbolAddress((void**)&x1,     g_x1);
    cudaGetSymbolAddress((void**)&xl2,    g_xl2);
    cudaGetSymbolAddress((void**)&xr2,    g_xr2);
    cudaGetSymbolAddress((void**)&x2,     g_x2);
    cudaGetSymbolAddress((void**)&deg,    g_deg);
    cudaGetSymbolAddress((void**)&rowptr, g_rowptr);
    cudaGetSymbolAddress((void**)&cnt,    g_cnt);
    cudaGetSymbolAddress((void**)&csr,    g_csr);

    // --- CSR build (dst-sorted incoming edges, self loops appended) ---
    k_zero_int<<<(NN + 255) / 256, 256>>>(deg, NN);
    k_hist<<<(ETOT + 255) / 256, 256>>>(ei, deg);
    k_scan<<<1, 512>>>(deg, rowptr);
    k_zero_int<<<(NN + 255) / 256, 256>>>(cnt, NN);
    k_scatter<<<(ETOT + 255) / 256, 256>>>(ei, rowptr, cnt, csr);

    // --- embed gather + concat + projection (relu) ---
    k_combined<<<(NN * KIN + 255) / 256, 256>>>(xp, emb, comb);
    k_gemm64<<<dim3(1, (NN + 63) / 64), 256>>>(comb, proj_W, proj_b, x0, NN, HID, KIN, 1);

    // --- GAT layer 1: 4 heads x 128 ---
    k_gemm128<<<dim3(4, (NN + 127) / 128), 256>>>(x0, W1l, xl1, NN, 512, HID);
    k_gemm128<<<dim3(4, (NN + 127) / 128), 256>>>(x0, W1r, xr1, NN, 512, HID);
    k_gat<4, true><<<NN, 128>>>(xl1, xr1, att1, b1, rowptr, csr, x1);

    // --- GAT layer 2: 1 head x 128 ---
    k_gemm64<<<dim3(1, (NN + 63) / 64), 256>>>(x1, W2l, nullptr, xl2, NN, HID, 512, 0);
    k_gemm64<<<dim3(1, (NN + 63) / 64), 256>>>(x1, W2r, nullptr, xr2, NN, HID, 512, 0);
    k_gat<1, false><<<NN, 128>>>(xl2, xr2, att2, b2, rowptr, csr, x2);

    // --- output head ---
    k_out<<<(NN + 7) / 8, 256>>>(x2, out_W, out_b, out);
}

// round 4
// speedup vs baseline: 1.2662x; 1.2662x over previous
#include <cuda_runtime.h>
#include <cuda_bf16.h>
#include <cstdint>
#include <math.h>

#define NN   20000
#define EE   320000
#define ETOT (EE + NN)
#define FEAT 64
#define HID  128
#define OUTD 10
#define KIN  (HID + FEAT)   // 192

// ================= scratch (static device memory) =================
__device__ __nv_bfloat16 g_combhi[NN * KIN];
__device__ __nv_bfloat16 g_comblo[NN * KIN];
__device__ __nv_bfloat16 g_x0hi[NN * HID];
__device__ __nv_bfloat16 g_x0lo[NN * HID];
__device__ float         g_xlr1[NN * 1024];
__device__ __nv_bfloat16 g_x1hi[NN * 512];
__device__ __nv_bfloat16 g_x1lo[NN * 512];
__device__ float         g_xlr2[NN * 256];
__device__ float         g_x2  [NN * HID];
__device__ __nv_bfloat16 g_bproj[128 * 3 * KIN];
__device__ __nv_bfloat16 g_b1   [1024 * 3 * HID];
__device__ __nv_bfloat16 g_b2   [256 * 3 * 512];
__device__ int g_deg[NN];
__device__ int g_rowptr[NN + 1];
__device__ int g_cnt[NN];
__device__ int g_csr[ETOT];

// ================= CSR build =================
__global__ void k_zero_int(int* p, int n) {
    int i = blockIdx.x * blockDim.x + threadIdx.x;
    if (i < n) p[i] = 0;
}
__global__ void k_hist(const int* __restrict__ ei, int* __restrict__ deg) {
    int i = blockIdx.x * blockDim.x + threadIdx.x;
    if (i >= ETOT) return;
    int d = (i < EE) ? ei[EE + i] : (i - EE);
    atomicAdd(&deg[d], 1);
}
__global__ void k_scan(const int* __restrict__ deg, int* __restrict__ rowptr) {
    __shared__ int sh[512];
    const int VPT = (NN + 511) / 512;
    int t = threadIdx.x;
    int base = t * VPT;
    int sum = 0;
    for (int j = 0; j < VPT; j++) { int i = base + j; if (i < NN) sum += deg[i]; }
    sh[t] = sum;
    __syncthreads();
    for (int off = 1; off < 512; off <<= 1) {
        int v = (t >= off) ? sh[t - off] : 0;
        __syncthreads();
        sh[t] += v;
        __syncthreads();
    }
    int run = (t == 0) ? 0 : sh[t - 1];
    for (int j = 0; j < VPT; j++) {
        int i = base + j;
        if (i < NN) { rowptr[i] = run; run += deg[i]; }
    }
    if (t == 511) rowptr[NN] = sh[511];
}
__global__ void k_scatter(const int* __restrict__ ei, const int* __restrict__ rowptr,
                          int* __restrict__ cnt, int* __restrict__ csr) {
    int i = blockIdx.x * blockDim.x + threadIdx.x;
    if (i >= ETOT) return;
    int s, d;
    if (i < EE) { s = ei[i]; d = ei[EE + i]; }
    else        { s = d = i - EE; }
    int p = rowptr[d] + atomicAdd(&cnt[d], 1);
    csr[p] = s;
}

// ================= split helpers =================
__device__ __forceinline__ void split2(float v, __nv_bfloat16& hi, __nv_bfloat16& lo) {
    hi = __float2bfloat16_rn(v);
    lo = __float2bfloat16_rn(v - __bfloat162float(hi));
}

// weights: B0 [K, Nper] (optionally B1 [K, Nper]) -> out [Ntot, 3K] bf16: [hi | lo | hi]
__global__ void k_split_w(const float* __restrict__ B0, const float* __restrict__ B1,
                          int K, int Nper, int Ntot, __nv_bfloat16* __restrict__ out) {
    int idx = blockIdx.x * blockDim.x + threadIdx.x;
    if (idx >= Ntot * K) return;
    int n = idx / K, k = idx - n * K;
    float v = (n < Nper) ? B0[(size_t)k * Nper + n] : B1[(size_t)k * Nper + (n - Nper)];
    __nv_bfloat16 hi, lo;
    split2(v, hi, lo);
    size_t base = (size_t)n * 3 * K;
    out[base + k] = hi;
    out[base + K + k] = lo;
    out[base + 2 * K + k] = hi;
}

// combined = [emb[ids], feats] -> hi/lo bf16
__global__ void k_combined_split(const float* __restrict__ xp, const float* __restrict__ emb,
                                 __nv_bfloat16* __restrict__ chi, __nv_bfloat16* __restrict__ clo) {
    int idx = blockIdx.x * blockDim.x + threadIdx.x;
    if (idx >= NN * KIN) return;
    int i = idx / KIN;
    int k = idx - i * KIN;
    float v;
    if (k < HID) {
        int id = (int)xp[i * (FEAT + 1)];
        v = emb[(size_t)id * HID + k];
    } else {
        v = xp[i * (FEAT + 1) + 1 + (k - HID)];
    }
    __nv_bfloat16 hi, lo;
    split2(v, hi, lo);
    chi[idx] = hi;
    clo[idx] = lo;
}

// ================= HMMA split-bf16 GEMM =================
// C[M, Ntot] = A[M,K] @ Borig[K,Ntot]  via 3 bf16 products.
// A: Ahi/Alo [M,K] bf16 row-major. Bs: [Ntot, 3K] bf16 ([hi|lo|hi]) k-contiguous ("col" layout).
// Block 128x128, BK=32, 8 warps (4x2), warp tile 32x64.
#define SMP 40   // smem row pitch in bf16 elements (32 + 8 pad)

__device__ __forceinline__ void mma16816(float* c, const uint32_t* a, const uint32_t* b) {
    asm volatile(
        "mma.sync.aligned.m16n8k16.row.col.f32.bf16.bf16.f32 "
        "{%0,%1,%2,%3}, {%4,%5,%6,%7}, {%8,%9}, {%0,%1,%2,%3};"
        : "+f"(c[0]), "+f"(c[1]), "+f"(c[2]), "+f"(c[3])
        : "r"(a[0]), "r"(a[1]), "r"(a[2]), "r"(a[3]), "r"(b[0]), "r"(b[1]));
}

template <bool SPLIT_OUT>
__global__ void __launch_bounds__(256) k_gemm_mma(
    const __nv_bfloat16* __restrict__ Ahi, const __nv_bfloat16* __restrict__ Alo,
    const __nv_bfloat16* __restrict__ Bs,
    float* __restrict__ C,
    __nv_bfloat16* __restrict__ Chi, __nv_bfloat16* __restrict__ Clo,
    const float* __restrict__ bias, int relu,
    int M, int Ntot, int K) {
    __shared__ __nv_bfloat16 As[128][SMP];
    __shared__ __nv_bfloat16 Bsh[128][SMP];

    int tid = threadIdx.x;
    int warp = tid >> 5, lane = tid & 31;
    int warpM = warp >> 1, warpN = warp & 1;     // 4 x 2
    int groupID = lane >> 2, tig = lane & 3;
    int brow = blockIdx.y * 128, bcol = blockIdx.x * 128;

    float acc[2][8][4];
#pragma unroll
    for (int mt = 0; mt < 2; mt++)
#pragma unroll
        for (int nt = 0; nt < 8; nt++)
#pragma unroll
            for (int q = 0; q < 4; q++) acc[mt][nt][q] = 0.f;

    int lrow = tid >> 1;        // 0..127
    int lhalf = tid & 1;        // each loads 16 bf16 = 2 x uint4

    const int kc = K >> 5;      // chunks of 32 per segment
    const int nc = 3 * kc;
    const int B3K = 3 * K;
    int grA = brow + lrow;
    bool aok = grA < M;

    for (int c = 0; c < nc; c++) {
        int seg = c / kc;
        int cw = c - seg * kc;
        const __nv_bfloat16* Ap = (seg < 2) ? Ahi : Alo;
        int ak = cw << 5;
        int bk = seg * K + (cw << 5);

        uint4 av0 = make_uint4(0, 0, 0, 0), av1 = make_uint4(0, 0, 0, 0);
        if (aok) {
            const __nv_bfloat16* arow = Ap + (size_t)grA * K + ak + lhalf * 16;
            av0 = *(const uint4*)(arow);
            av1 = *(const uint4*)(arow + 8);
        }
        const __nv_bfloat16* brp = Bs + (size_t)(bcol + lrow) * B3K + bk + lhalf * 16;
        uint4 bv0 = *(const uint4*)(brp);
        uint4 bv1 = *(const uint4*)(brp + 8);

        *(uint4*)&As[lrow][lhalf * 16]      = av0;
        *(uint4*)&As[lrow][lhalf * 16 + 8]  = av1;
        *(uint4*)&Bsh[lrow][lhalf * 16]     = bv0;
        *(uint4*)&Bsh[lrow][lhalf * 16 + 8] = bv1;
        __syncthreads();

#pragma unroll
        for (int ko = 0; ko < 32; ko += 16) {
            uint32_t af[2][4];
#pragma unroll
            for (int mt = 0; mt < 2; mt++) {
                int r0 = warpM * 32 + mt * 16 + groupID;
                af[mt][0] = *(const uint32_t*)&As[r0][ko + 2 * tig];
                af[mt][1] = *(const uint32_t*)&As[r0 + 8][ko + 2 * tig];
                af[mt][2] = *(const uint32_t*)&As[r0][ko + 2 * tig + 8];
                af[mt][3] = *(const uint32_t*)&As[r0 + 8][ko + 2 * tig + 8];
            }
            uint32_t bfr[8][2];
#pragma unroll
            for (int nt = 0; nt < 8; nt++) {
                int cn = warpN * 64 + nt * 8 + groupID;
                bfr[nt][0] = *(const uint32_t*)&Bsh[cn][ko + 2 * tig];
                bfr[nt][1] = *(const uint32_t*)&Bsh[cn][ko + 2 * tig + 8];
            }
#pragma unroll
            for (int mt = 0; mt < 2; mt++)
#pragma unroll
                for (int nt = 0; nt < 8; nt++)
                    mma16816(acc[mt][nt], af[mt], bfr[nt]);
        }
        __syncthreads();
    }

    // epilogue
#pragma unroll
    for (int mt = 0; mt < 2; mt++) {
        int r0 = brow + warpM * 32 + mt * 16 + groupID;
#pragma unroll
        for (int half = 0; half < 2; half++) {
            int r = r0 + half * 8;
            if (r >= M) continue;
#pragma unroll
            for (int nt = 0; nt < 8; nt++) {
                int cn = bcol + warpN * 64 + nt * 8 + 2 * tig;
                float v0 = acc[mt][nt][half * 2];
                float v1 = acc[mt][nt][half * 2 + 1];
                if (!SPLIT_OUT) {
                    *(float2*)(C + (size_t)r * Ntot + cn) = make_float2(v0, v1);
                } else {
                    if (bias) { v0 += bias[cn]; v1 += bias[cn + 1]; }
                    if (relu) { v0 = fmaxf(v0, 0.f); v1 = fmaxf(v1, 0.f); }
                    __nv_bfloat16 h0, l0, h1, l1;
                    split2(v0, h0, l0);
                    split2(v1, h1, l1);
                    size_t o = (size_t)r * Ntot + cn;
                    Chi[o] = h0; Chi[o + 1] = h1;
                    Clo[o] = l0; Clo[o + 1] = l1;
                }
            }
        }
    }
}

// ================= GATv2 per-dst-node, online softmax =================
template <int HEADS, bool RELU, bool SPLIT>
__global__ void __launch_bounds__(128) k_gat(
    const float* __restrict__ xl, const float* __restrict__ xr, int xstride,
    const float* __restrict__ att, const float* __restrict__ bias,
    const int* __restrict__ rowptr, const int* __restrict__ csr,
    float* __restrict__ outf,
    __nv_bfloat16* __restrict__ outhi, __nv_bfloat16* __restrict__ outlo) {
    int node = blockIdx.x;
    int t = threadIdx.x;
    int lane = t & 31, warp = t >> 5;
    __shared__ float xr_sh[HEADS * 128];
    __shared__ float att_sh[HEADS * 128];
    __shared__ float red[4 * HEADS];
    __shared__ float bcast[HEADS];
#pragma unroll
    for (int h = 0; h < HEADS; h++) {
        xr_sh[h * 128 + t]  = xr[(size_t)node * xstride + h * 128 + t];
        att_sh[h * 128 + t] = att[h * 128 + t];
    }
    __syncthreads();
    float m[HEADS], s[HEADS], acc[HEADS];
#pragma unroll
    for (int h = 0; h < HEADS; h++) { m[h] = -INFINITY; s[h] = 0.f; acc[h] = 0.f; }
    int beg = rowptr[node], end = rowptr[node + 1];
    for (int i = beg; i < end; i++) {
        int src = csr[i];
        const float* xlp = xl + (size_t)src * xstride;
        float xlv[HEADS], p[HEADS];
#pragma unroll
        for (int h = 0; h < HEADS; h++) {
            xlv[h] = xlp[h * 128 + t];
            float v = xlv[h] + xr_sh[h * 128 + t];
            v = (v > 0.f) ? v : 0.2f * v;
            p[h] = v * att_sh[h * 128 + t];
        }
#pragma unroll
        for (int h = 0; h < HEADS; h++)
#pragma unroll
            for (int off = 16; off > 0; off >>= 1)
                p[h] += __shfl_down_sync(0xffffffffu, p[h], off);
        if (lane == 0) {
#pragma unroll
            for (int h = 0; h < HEADS; h++) red[warp * HEADS + h] = p[h];
        }
        __syncthreads();
        if (t < HEADS)
            bcast[t] = red[t] + red[HEADS + t] + red[2 * HEADS + t] + red[3 * HEADS + t];
        __syncthreads();
#pragma unroll
        for (int h = 0; h < HEADS; h++) {
            float e = bcast[h];
            float mn = fmaxf(m[h], e);
            float cs = __expf(m[h] - mn);
            float w  = __expf(e - mn);
            s[h]   = s[h] * cs + w;
            acc[h] = acc[h] * cs + w * xlv[h];
            m[h]   = mn;
        }
        __syncthreads();
    }
#pragma unroll
    for (int h = 0; h < HEADS; h++) {
        float o = acc[h] / (s[h] + 1e-16f) + bias[h * 128 + t];
        if (RELU) o = fmaxf(o, 0.f);
        size_t oidx = (size_t)node * HEADS * 128 + h * 128 + t;
        if (SPLIT) {
            __nv_bfloat16 hi, lo;
            split2(o, hi, lo);
            outhi[oidx] = hi;
            outlo[oidx] = lo;
        } else {
            outf[oidx] = o;
        }
    }
}

// ================= output head: [N,128] @ [128,10] + b =================
__global__ void __launch_bounds__(256) k_out(const float* __restrict__ x2,
                                             const float* __restrict__ W,
                                             const float* __restrict__ b,
                                             float* __restrict__ out) {
    int warp = threadIdx.x >> 5, lane = threadIdx.x & 31;
    int node = blockIdx.x * 8 + warp;
    if (node >= NN) return;
    float4 xv = *(const float4*)(x2 + (size_t)node * HID + lane * 4);
    float a[4] = {xv.x, xv.y, xv.z, xv.w};
    float acc[OUTD];
#pragma unroll
    for (int j = 0; j < OUTD; j++) acc[j] = 0.f;
#pragma unroll
    for (int q = 0; q < 4; q++) {
        int k = lane * 4 + q;
        float x = a[q];
#pragma unroll
        for (int j = 0; j < OUTD; j++) acc[j] += x * W[k * OUTD + j];
    }
#pragma unroll
    for (int j = 0; j < OUTD; j++)
#pragma unroll
        for (int off = 16; off > 0; off >>= 1)
            acc[j] += __shfl_down_sync(0xffffffffu, acc[j], off);
    if (lane == 0) {
#pragma unroll
        for (int j = 0; j < OUTD; j++) out[(size_t)node * OUTD + j] = acc[j] + b[j];
    }
}

// ================= launcher =================
extern "C" void kernel_launch(void* const* d_in, const int* in_sizes, int n_in,
                              void* d_out, int out_size) {
    const float* xp     = (const float*)d_in[0];
    const int*   ei     = (const int*)  d_in[1];
    const float* emb    = (const float*)d_in[2];
    const float* proj_W = (const float*)d_in[3];
    const float* proj_b = (const float*)d_in[4];
    const float* W1l    = (const float*)d_in[5];
    const float* W1r    = (const float*)d_in[6];
    const float* att1   = (const float*)d_in[7];
    const float* b1     = (const float*)d_in[8];
    const float* W2l    = (const float*)d_in[9];
    const float* W2r    = (const float*)d_in[10];
    const float* att2   = (const float*)d_in[11];
    const float* b2     = (const float*)d_in[12];
    const float* out_W  = (const float*)d_in[13];
    const float* out_b  = (const float*)d_in[14];
    float* out = (float*)d_out;

    __nv_bfloat16 *combhi, *comblo, *x0hi, *x0lo, *x1hi, *x1lo, *bproj, *bw1, *bw2;
    float *xlr1, *xlr2, *x2;
    int *deg, *rowptr, *cnt, *csr;
    cudaGetSymbolAddress((void**)&combhi, g_combhi);
    cudaGetSymbolAddress((void**)&comblo, g_comblo);
    cudaGetSymbolAddress((void**)&x0hi,   g_x0hi);
    cudaGetSymbolAddress((void**)&x0lo,   g_x0lo);
    cudaGetSymbolAddress((void**)&xlr1,   g_xlr1);
    cudaGetSymbolAddress((void**)&x1hi,   g_x1hi);
    cudaGetSymbolAddress((void**)&x1lo,   g_x1lo);
    cudaGetSymbolAddress((void**)&xlr2,   g_xlr2);
    cudaGetSymbolAddress((void**)&x2,     g_x2);
    cudaGetSymbolAddress((void**)&bproj,  g_bproj);
    cudaGetSymbolAddress((void**)&bw1,    g_b1);
    cudaGetSymbolAddress((void**)&bw2,    g_b2);
    cudaGetSymbolAddress((void**)&deg,    g_deg);
    cudaGetSymbolAddress((void**)&rowptr, g_rowptr);
    cudaGetSymbolAddress((void**)&cnt,    g_cnt);
    cudaGetSymbolAddress((void**)&csr,    g_csr);

    // --- CSR build ---
    k_zero_int<<<(NN + 255) / 256, 256>>>(deg, NN);
    k_hist<<<(ETOT + 255) / 256, 256>>>(ei, deg);
    k_scan<<<1, 512>>>(deg, rowptr);
    k_zero_int<<<(NN + 255) / 256, 256>>>(cnt, NN);
    k_scatter<<<(ETOT + 255) / 256, 256>>>(ei, rowptr, cnt, csr);

    // --- weight transpose + split ---
    k_split_w<<<(128 * KIN + 255) / 256, 256>>>(proj_W, nullptr, KIN, 128, 128, bproj);
    k_split_w<<<(1024 * HID + 255) / 256, 256>>>(W1l, W1r, HID, 512, 1024, bw1);
    k_split_w<<<(256 * 512 + 255) / 256, 256>>>(W2l, W2r, 512, 128, 256, bw2);

    // --- gather/concat -> split bf16 ---
    k_combined_split<<<(NN * KIN + 255) / 256, 256>>>(xp, emb, combhi, comblo);

    const int MB = (NN + 127) / 128;   // 157

    // --- proj: [N,192]@[192,128] + b, relu, split output ---
    k_gemm_mma<true><<<dim3(1, MB), 256>>>(combhi, comblo, bproj,
                                           nullptr, x0hi, x0lo, proj_b, 1,
                                           NN, 128, KIN);

    // --- layer 1: x0 @ [W1l|W1r] -> [N,1024] fp32 ---
    k_gemm_mma<false><<<dim3(8, MB), 256>>>(x0hi, x0lo, bw1,
                                            xlr1, nullptr, nullptr, nullptr, 0,
                                            NN, 1024, HID);
    k_gat<4, true, true><<<NN, 128>>>(xlr1, xlr1 + 512, 1024, att1, b1,
                                      rowptr, csr, nullptr, x1hi, x1lo);

    // --- layer 2: x1 @ [W2l|W2r] -> [N,256] fp32 ---
    k_gemm_mma<false><<<dim3(2, MB), 256>>>(x1hi, x1lo, bw2,
                                            xlr2, nullptr, nullptr, nullptr, 0,
                                            NN, 256, 512);
    k_gat<1, false, false><<<NN, 128>>>(xlr2, xlr2 + 128, 256, att2, b2,
                                        rowptr, csr, x2, nullptr, nullptr);

    // --- output head ---
    k_out<<<(NN + 7) / 8, 256>>>(x2, out_W, out_b, out);
}

// round 6
// speedup vs baseline: 2.0226x; 1.5975x over previous
#include <cuda_runtime.h>
#include <cuda_bf16.h>
#include <cstdint>
#include <math.h>

#define NN   20000
#define EE   320000
#define ETOT (EE + NN)
#define FEAT 64
#define HID  128
#define OUTD 10
#define KIN  (HID + FEAT)   // 192

// ================= scratch (static device memory) =================
__device__ __nv_bfloat16 g_combhi[NN * KIN];
__device__ __nv_bfloat16 g_comblo[NN * KIN];
__device__ __nv_bfloat16 g_x0hi[NN * HID];
__device__ __nv_bfloat16 g_x0lo[NN * HID];
__device__ float         g_xlr1[NN * 1024];
__device__ __nv_bfloat16 g_x1hi[NN * 512];
__device__ __nv_bfloat16 g_x1lo[NN * 512];
__device__ float         g_xlr2[NN * 256];
__device__ float         g_x2  [NN * HID];
__device__ __nv_bfloat16 g_bproj[128 * 3 * KIN];
__device__ __nv_bfloat16 g_b1   [1024 * 3 * HID];
__device__ __nv_bfloat16 g_b2   [256 * 3 * 512];
__device__ int g_deg[NN];
__device__ int g_rowptr[NN + 1];
__device__ int g_cnt[NN];
__device__ int g_csr[ETOT];

// ================= cp.async helpers =================
__device__ __forceinline__ uint32_t smem_u32(const void* p) {
    return (uint32_t)__cvta_generic_to_shared(p);
}
#define CP_A16(sa, gp, n) asm volatile("cp.async.cg.shared.global [%0], [%1], 16, %2;" :: "r"(sa), "l"(gp), "r"(n))
#define CP_COMMIT()       asm volatile("cp.async.commit_group;")
#define CP_WAIT1()        asm volatile("cp.async.wait_group 1;")
#define CP_WAIT0()        asm volatile("cp.async.wait_group 0;")

// ================= CSR build =================
__global__ void k_zero_int(int* p, int n) {
    int i = blockIdx.x * blockDim.x + threadIdx.x;
    if (i < n) p[i] = 0;
}
__global__ void k_hist(const int* __restrict__ ei, int* __restrict__ deg) {
    int i = blockIdx.x * blockDim.x + threadIdx.x;
    if (i >= ETOT) return;
    int d = (i < EE) ? ei[EE + i] : (i - EE);
    atomicAdd(&deg[d], 1);
}
__global__ void k_scan(const int* __restrict__ deg, int* __restrict__ rowptr) {
    __shared__ int sh[512];
    const int VPT = (NN + 511) / 512;
    int t = threadIdx.x;
    int base = t * VPT;
    int sum = 0;
    for (int j = 0; j < VPT; j++) { int i = base + j; if (i < NN) sum += deg[i]; }
    sh[t] = sum;
    __syncthreads();
    for (int off = 1; off < 512; off <<= 1) {
        int v = (t >= off) ? sh[t - off] : 0;
        __syncthreads();
        sh[t] += v;
        __syncthreads();
    }
    int run = (t == 0) ? 0 : sh[t - 1];
    for (int j = 0; j < VPT; j++) {
        int i = base + j;
        if (i < NN) { rowptr[i] = run; run += deg[i]; }
    }
    if (t == 511) rowptr[NN] = sh[511];
}
__global__ void k_scatter(const int* __restrict__ ei, const int* __restrict__ rowptr,
                          int* __restrict__ cnt, int* __restrict__ csr) {
    int i = blockIdx.x * blockDim.x + threadIdx.x;
    if (i >= ETOT) return;
    int s, d;
    if (i < EE) { s = ei[i]; d = ei[EE + i]; }
    else        { s = d = i - EE; }
    int p = rowptr[d] + atomicAdd(&cnt[d], 1);
    csr[p] = s;
}

// ================= split helpers =================
__device__ __forceinline__ void split2(float v, __nv_bfloat16& hi, __nv_bfloat16& lo) {
    hi = __float2bfloat16_rn(v);
    lo = __float2bfloat16_rn(v - __bfloat162float(hi));
}

__global__ void k_split_w(const float* __restrict__ B0, const float* __restrict__ B1,
                          int K, int Nper, int Ntot, __nv_bfloat16* __restrict__ out) {
    int idx = blockIdx.x * blockDim.x + threadIdx.x;
    if (idx >= Ntot * K) return;
    int n = idx / K, k = idx - n * K;
    float v = (n < Nper) ? B0[(size_t)k * Nper + n] : B1[(size_t)k * Nper + (n - Nper)];
    __nv_bfloat16 hi, lo;
    split2(v, hi, lo);
    size_t base = (size_t)n * 3 * K;
    out[base + k] = hi;
    out[base + K + k] = lo;
    out[base + 2 * K + k] = hi;
}

__global__ void k_combined_split(const float* __restrict__ xp, const float* __restrict__ emb,
                                 __nv_bfloat16* __restrict__ chi, __nv_bfloat16* __restrict__ clo) {
    int idx = blockIdx.x * blockDim.x + threadIdx.x;
    if (idx >= NN * KIN) return;
    int i = idx / KIN;
    int k = idx - i * KIN;
    float v;
    if (k < HID) {
        int id = (int)xp[i * (FEAT + 1)];
        v = emb[(size_t)id * HID + k];
    } else {
        v = xp[i * (FEAT + 1) + 1 + (k - HID)];
    }
    __nv_bfloat16 hi, lo;
    split2(v, hi, lo);
    chi[idx] = hi;
    clo[idx] = lo;
}

// ================= HMMA split-bf16 GEMM, cp.async double-buffered =================
#define SMP 40   // smem row pitch in bf16 (32 + 8 pad)

__device__ __forceinline__ void mma16816(float* c, const uint32_t* a, const uint32_t* b) {
    asm volatile(
        "mma.sync.aligned.m16n8k16.row.col.f32.bf16.bf16.f32 "
        "{%0,%1,%2,%3}, {%4,%5,%6,%7}, {%8,%9}, {%0,%1,%2,%3};"
        : "+f"(c[0]), "+f"(c[1]), "+f"(c[2]), "+f"(c[3])
        : "r"(a[0]), "r"(a[1]), "r"(a[2]), "r"(a[3]), "r"(b[0]), "r"(b[1]));
}

template <bool SPLIT_OUT>
__global__ void __launch_bounds__(256) k_gemm_mma(
    const __nv_bfloat16* __restrict__ Ahi, const __nv_bfloat16* __restrict__ Alo,
    const __nv_bfloat16* __restrict__ Bs,
    float* __restrict__ C,
    __nv_bfloat16* __restrict__ Chi, __nv_bfloat16* __restrict__ Clo,
    const float* __restrict__ bias, int relu,
    int M, int Ntot, int K) {
    __shared__ __nv_bfloat16 As[2][128][SMP];
    __shared__ __nv_bfloat16 Bsh[2][128][SMP];

    int tid = threadIdx.x;
    int warp = tid >> 5, lane = tid & 31;
    int warpM = warp >> 1, warpN = warp & 1;     // 4 x 2
    int groupID = lane >> 2, tig = lane & 3;
    int brow = blockIdx.y * 128, bcol = blockIdx.x * 128;

    float acc[2][8][4];
#pragma unroll
    for (int mt = 0; mt < 2; mt++)
#pragma unroll
        for (int nt = 0; nt < 8; nt++)
#pragma unroll
            for (int q = 0; q < 4; q++) acc[mt][nt][q] = 0.f;

    int lrow = tid >> 1;
    int lhalf = tid & 1;

    const int kc = K >> 5;
    const int nc = 3 * kc;
    const int B3K = 3 * K;
    int grA = brow + lrow;
    bool aok = grA < M;
    int asz = aok ? 16 : 0;
    const __nv_bfloat16* arow_safe_hi = Ahi + (size_t)(aok ? grA : 0) * K;
    const __nv_bfloat16* arow_safe_lo = Alo + (size_t)(aok ? grA : 0) * K;
    const __nv_bfloat16* brow_base = Bs + (size_t)(bcol + lrow) * B3K;

    // issue loads for chunk c into buffer buf
    auto issue = [&](int c, int buf) {
        int seg = c / kc;
        int cw = c - seg * kc;
        const __nv_bfloat16* Ap = (seg < 2) ? arow_safe_hi : arow_safe_lo;
        const __nv_bfloat16* ap = Ap + (cw << 5) + lhalf * 16;
        const __nv_bfloat16* bp = brow_base + seg * K + (cw << 5) + lhalf * 16;
        uint32_t ad = smem_u32(&As[buf][lrow][lhalf * 16]);
        uint32_t bd = smem_u32(&Bsh[buf][lrow][lhalf * 16]);
        CP_A16(ad, ap, asz);
        CP_A16(ad + 16, ap + 8, asz);
        CP_A16(bd, bp, 16);
        CP_A16(bd + 16, bp + 8, 16);
    };

    issue(0, 0);
    CP_COMMIT();

    for (int c = 0; c < nc; c++) {
        int buf = c & 1;
        if (c + 1 < nc) {
            issue(c + 1, buf ^ 1);
            CP_COMMIT();
            CP_WAIT1();
        } else {
            CP_WAIT0();
        }
        __syncthreads();

#pragma unroll
        for (int ko = 0; ko < 32; ko += 16) {
            uint32_t af[2][4];
#pragma unroll
            for (int mt = 0; mt < 2; mt++) {
                int r0 = warpM * 32 + mt * 16 + groupID;
                af[mt][0] = *(const uint32_t*)&As[buf][r0][ko + 2 * tig];
                af[mt][1] = *(const uint32_t*)&As[buf][r0 + 8][ko + 2 * tig];
                af[mt][2] = *(const uint32_t*)&As[buf][r0][ko + 2 * tig + 8];
                af[mt][3] = *(const uint32_t*)&As[buf][r0 + 8][ko + 2 * tig + 8];
            }
            uint32_t bfr[8][2];
#pragma unroll
            for (int nt = 0; nt < 8; nt++) {
                int cn = warpN * 64 + nt * 8 + groupID;
                bfr[nt][0] = *(const uint32_t*)&Bsh[buf][cn][ko + 2 * tig];
                bfr[nt][1] = *(const uint32_t*)&Bsh[buf][cn][ko + 2 * tig + 8];
            }
#pragma unroll
            for (int mt = 0; mt < 2; mt++)
#pragma unroll
                for (int nt = 0; nt < 8; nt++)
                    mma16816(acc[mt][nt], af[mt], bfr[nt]);
        }
        __syncthreads();
    }

    // epilogue
#pragma unroll
    for (int mt = 0; mt < 2; mt++) {
        int r0 = brow + warpM * 32 + mt * 16 + groupID;
#pragma unroll
        for (int half = 0; half < 2; half++) {
            int r = r0 + half * 8;
            if (r >= M) continue;
#pragma unroll
            for (int nt = 0; nt < 8; nt++) {
                int cn = bcol + warpN * 64 + nt * 8 + 2 * tig;
                float v0 = acc[mt][nt][half * 2];
                float v1 = acc[mt][nt][half * 2 + 1];
                if (!SPLIT_OUT) {
                    *(float2*)(C + (size_t)r * Ntot + cn) = make_float2(v0, v1);
                } else {
                    if (bias) { v0 += bias[cn]; v1 += bias[cn + 1]; }
                    if (relu) { v0 = fmaxf(v0, 0.f); v1 = fmaxf(v1, 0.f); }
                    __nv_bfloat16 h0, l0, h1, l1;
                    split2(v0, h0, l0);
                    split2(v1, h1, l1);
                    size_t o = (size_t)r * Ntot + cn;
                    Chi[o] = h0; Chi[o + 1] = h1;
                    Clo[o] = l0; Clo[o + 1] = l1;
                }
            }
        }
    }
}

// ================= GATv2: warp per (node, head), no barriers =================
// xl/xr rows inside [M, xstride] fp32. Each lane owns 4 channels (float4).
template <int HEADS, bool RELU, bool SPLIT>
__global__ void __launch_bounds__(128) k_gat_warp(
    const float* __restrict__ xl, const float* __restrict__ xr, int xstride,
    const float* __restrict__ att, const float* __restrict__ bias,
    const int* __restrict__ rowptr, const int* __restrict__ csr,
    float* __restrict__ outf,
    __nv_bfloat16* __restrict__ outhi, __nv_bfloat16* __restrict__ outlo) {
    int warp = threadIdx.x >> 5, lane = threadIdx.x & 31;
    int gw = blockIdx.x * 4 + warp;           // global warp id
    int node = gw / HEADS;
    int h = gw - node * HEADS;
    if (node >= NN) return;

    int co = h * 128 + lane * 4;              // channel offset within row
    float4 xr4  = *(const float4*)(xr + (size_t)node * xstride + co);
    float4 att4 = *(const float4*)(att + co);

    float m = -INFINITY, s = 0.f;
    float4 acc = make_float4(0.f, 0.f, 0.f, 0.f);

    int beg = rowptr[node], end = rowptr[node + 1];
    int src_n = csr[beg];
    float4 x_n = *(const float4*)(xl + (size_t)src_n * xstride + co);

    for (int i = beg; i < end; i++) {
        float4 xc = x_n;
        if (i + 1 < end) {
            int sn = csr[i + 1];
            x_n = *(const float4*)(xl + (size_t)sn * xstride + co);
        }
        float v0 = xc.x + xr4.x, v1 = xc.y + xr4.y, v2 = xc.z + xr4.z, v3 = xc.w + xr4.w;
        v0 = (v0 > 0.f) ? v0 : 0.2f * v0;
        v1 = (v1 > 0.f) ? v1 : 0.2f * v1;
        v2 = (v2 > 0.f) ? v2 : 0.2f * v2;
        v3 = (v3 > 0.f) ? v3 : 0.2f * v3;
        float p = v0 * att4.x + v1 * att4.y + v2 * att4.z + v3 * att4.w;
#pragma unroll
        for (int off = 16; off > 0; off >>= 1)
            p += __shfl_xor_sync(0xffffffffu, p, off);
        float e = p;
        float mn = fmaxf(m, e);
        float cs = __expf(m - mn);
        float w  = __expf(e - mn);
        s = s * cs + w;
        acc.x = acc.x * cs + w * xc.x;
        acc.y = acc.y * cs + w * xc.y;
        acc.z = acc.z * cs + w * xc.z;
        acc.w = acc.w * cs + w * xc.w;
        m = mn;
    }

    float inv = 1.f / (s + 1e-16f);
    float4 b4 = *(const float4*)(bias + co);
    float o0 = acc.x * inv + b4.x;
    float o1 = acc.y * inv + b4.y;
    float o2 = acc.z * inv + b4.z;
    float o3 = acc.w * inv + b4.w;
    if (RELU) {
        o0 = fmaxf(o0, 0.f); o1 = fmaxf(o1, 0.f);
        o2 = fmaxf(o2, 0.f); o3 = fmaxf(o3, 0.f);
    }
    size_t oidx = (size_t)node * (HEADS * 128) + co;
    if (SPLIT) {
        __nv_bfloat16 hh[4], ll[4];
        split2(o0, hh[0], ll[0]);
        split2(o1, hh[1], ll[1]);
        split2(o2, hh[2], ll[2]);
        split2(o3, hh[3], ll[3]);
        *(uint2*)(outhi + oidx) = *(uint2*)hh;
        *(uint2*)(outlo + oidx) = *(uint2*)ll;
    } else {
        *(float4*)(outf + oidx) = make_float4(o0, o1, o2, o3);
    }
}

// ================= output head: [N,128] @ [128,10] + b =================
__global__ void __launch_bounds__(256) k_out(const float* __restrict__ x2,
                                             const float* __restrict__ W,
                                             const float* __restrict__ b,
                                             float* __restrict__ out) {
    int warp = threadIdx.x >> 5, lane = threadIdx.x & 31;
    int node = blockIdx.x * 8 + warp;
    if (node >= NN) return;
    float4 xv = *(const float4*)(x2 + (size_t)node * HID + lane * 4);
    float a[4] = {xv.x, xv.y, xv.z, xv.w};
    float acc[OUTD];
#pragma unroll
    for (int j = 0; j < OUTD; j++) acc[j] = 0.f;
#pragma unroll
    for (int q = 0; q < 4; q++) {
        int k = lane * 4 + q;
        float x = a[q];
#pragma unroll
        for (int j = 0; j < OUTD; j++) acc[j] += x * W[k * OUTD + j];
    }
#pragma unroll
    for (int j = 0; j < OUTD; j++)
#pragma unroll
        for (int off = 16; off > 0; off >>= 1)
            acc[j] += __shfl_down_sync(0xffffffffu, acc[j], off);
    if (lane == 0) {
#pragma unroll
        for (int j = 0; j < OUTD; j++) out[(size_t)node * OUTD + j] = acc[j] + b[j];
    }
}

// ================= launcher =================
extern "C" void kernel_launch(void* const* d_in, const int* in_sizes, int n_in,
                              void* d_out, int out_size) {
    const float* xp     = (const float*)d_in[0];
    const int*   ei     = (const int*)  d_in[1];
    const float* emb    = (const float*)d_in[2];
    const float* proj_W = (const float*)d_in[3];
    const float* proj_b = (const float*)d_in[4];
    const float* W1l    = (const float*)d_in[5];
    const float* W1r    = (const float*)d_in[6];
    const float* att1   = (const float*)d_in[7];
    const float* b1     = (const float*)d_in[8];
    const float* W2l    = (const float*)d_in[9];
    const float* W2r    = (const float*)d_in[10];
    const float* att2   = (const float*)d_in[11];
    const float* b2     = (const float*)d_in[12];
    const float* out_W  = (const float*)d_in[13];
    const float* out_b  = (const float*)d_in[14];
    float* out = (float*)d_out;

    __nv_bfloat16 *combhi, *comblo, *x0hi, *x0lo, *x1hi, *x1lo, *bproj, *bw1, *bw2;
    float *xlr1, *xlr2, *x2;
    int *deg, *rowptr, *cnt, *csr;
    cudaGetSymbolAddress((void**)&combhi, g_combhi);
    cudaGetSymbolAddress((void**)&comblo, g_comblo);
    cudaGetSymbolAddress((void**)&x0hi,   g_x0hi);
    cudaGetSymbolAddress((void**)&x0lo,   g_x0lo);
    cudaGetSymbolAddress((void**)&xlr1,   g_xlr1);
    cudaGetSymbolAddress((void**)&x1hi,   g_x1hi);
    cudaGetSymbolAddress((void**)&x1lo,   g_x1lo);
    cudaGetSymbolAddress((void**)&xlr2,   g_xlr2);
    cudaGetSymbolAddress((void**)&x2,     g_x2);
    cudaGetSymbolAddress((void**)&bproj,  g_bproj);
    cudaGetSymbolAddress((void**)&bw1,    g_b1);
    cudaGetSymbolAddress((void**)&bw2,    g_b2);
    cudaGetSymbolAddress((void**)&deg,    g_deg);
    cudaGetSymbolAddress((void**)&rowptr, g_rowptr);
    cudaGetSymbolAddress((void**)&cnt,    g_cnt);
    cudaGetSymbolAddress((void**)&csr,    g_csr);

    // --- CSR build ---
    k_zero_int<<<(NN + 255) / 256, 256>>>(deg, NN);
    k_hist<<<(ETOT + 255) / 256, 256>>>(ei, deg);
    k_scan<<<1, 512>>>(deg, rowptr);
    k_zero_int<<<(NN + 255) / 256, 256>>>(cnt, NN);
    k_scatter<<<(ETOT + 255) / 256, 256>>>(ei, rowptr, cnt, csr);

    // --- weight transpose + split ---
    k_split_w<<<(128 * KIN + 255) / 256, 256>>>(proj_W, nullptr, KIN, 128, 128, bproj);
    k_split_w<<<(1024 * HID + 255) / 256, 256>>>(W1l, W1r, HID, 512, 1024, bw1);
    k_split_w<<<(256 * 512 + 255) / 256, 256>>>(W2l, W2r, 512, 128, 256, bw2);

    // --- gather/concat -> split bf16 ---
    k_combined_split<<<(NN * KIN + 255) / 256, 256>>>(xp, emb, combhi, comblo);

    const int MB = (NN + 127) / 128;   // 157

    // --- proj: [N,192]@[192,128] + b, relu, split output ---
    k_gemm_mma<true><<<dim3(1, MB), 256>>>(combhi, comblo, bproj,
                                           nullptr, x0hi, x0lo, proj_b, 1,
                                           NN, 128, KIN);

    // --- layer 1: x0 @ [W1l|W1r] -> [N,1024] fp32 ---
    k_gemm_mma<false><<<dim3(8, MB), 256>>>(x0hi, x0lo, bw1,
                                            xlr1, nullptr, nullptr, nullptr, 0,
                                            NN, 1024, HID);
    k_gat_warp<4, true, true><<<NN, 128>>>(xlr1, xlr1 + 512, 1024, att1, b1,
                                           rowptr, csr, nullptr, x1hi, x1lo);

    // --- layer 2: x1 @ [W2l|W2r] -> [N,256] fp32 ---
    k_gemm_mma<false><<<dim3(2, MB), 256>>>(x1hi, x1lo, bw2,
                                            xlr2, nullptr, nullptr, nullptr, 0,
                                            NN, 256, 512);
    k_gat_warp<1, false, false><<<(NN + 3) / 4, 128>>>(xlr2, xlr2 + 128, 256, att2, b2,
                                                       rowptr, csr, x2, nullptr, nullptr);

    // --- output head ---
    k_out<<<(NN + 7) / 8, 256>>>(x2, out_W, out_b, out);
}

// round 10
// speedup vs baseline: 2.0795x; 1.0281x over previous
#include <cuda_runtime.h>
#include <cuda_bf16.h>
#include <cstdint>
#include <math.h>

#define NN   20000
#define EE   320000
#define ETOT (EE + NN)
#define FEAT 64
#define HID  128
#define OUTD 10
#define KIN  (HID + FEAT)   // 192

// ================= scratch (static device memory) =================
__device__ __nv_bfloat16 g_combhi[NN * KIN];
__device__ __nv_bfloat16 g_comblo[NN * KIN];
__device__ __nv_bfloat16 g_x0hi[NN * HID];
__device__ __nv_bfloat16 g_x0lo[NN * HID];
__device__ float         g_xlr1[NN * 1024];
__device__ __nv_bfloat16 g_x1hi[NN * 512];
__device__ __nv_bfloat16 g_x1lo[NN * 512];
__device__ float         g_xlr2[NN * 256];
__device__ __nv_bfloat16 g_bproj[128 * 3 * KIN];
__device__ __nv_bfloat16 g_b1   [1024 * 3 * HID];
__device__ __nv_bfloat16 g_b2   [256 * 3 * 512];
__device__ int g_deg[NN];
__device__ int g_rowptr[NN + 1];
__device__ int g_cnt[NN];
__device__ int g_csr[ETOT];

// ================= asm helpers =================
__device__ __forceinline__ uint32_t smem_u32(const void* p) {
    return (uint32_t)__cvta_generic_to_shared(p);
}
#define CP_A16(sa, gp, n) asm volatile("cp.async.cg.shared.global [%0], [%1], 16, %2;" :: "r"(sa), "l"(gp), "r"(n))
#define CP_COMMIT()       asm volatile("cp.async.commit_group;")
#define CP_WAIT1()        asm volatile("cp.async.wait_group 1;")
#define CP_WAIT0()        asm volatile("cp.async.wait_group 0;")

__device__ __forceinline__ void ldm_x4(uint32_t* r, uint32_t a) {
    asm volatile("ldmatrix.sync.aligned.m8n8.x4.shared.b16 {%0,%1,%2,%3}, [%4];"
                 : "=r"(r[0]), "=r"(r[1]), "=r"(r[2]), "=r"(r[3]) : "r"(a));
}
__device__ __forceinline__ void mma16816(float* c, const uint32_t* a, const uint32_t* b) {
    asm volatile(
        "mma.sync.aligned.m16n8k16.row.col.f32.bf16.bf16.f32 "
        "{%0,%1,%2,%3}, {%4,%5,%6,%7}, {%8,%9}, {%0,%1,%2,%3};"
        : "+f"(c[0]), "+f"(c[1]), "+f"(c[2]), "+f"(c[3])
        : "r"(a[0]), "r"(a[1]), "r"(a[2]), "r"(a[3]), "r"(b[0]), "r"(b[1]));
}

// ================= CSR build =================
__global__ void k_zero_int(int* p, int n) {
    int i = blockIdx.x * blockDim.x + threadIdx.x;
    if (i < n) p[i] = 0;
}
__global__ void k_hist(const int* __restrict__ ei, int* __restrict__ deg) {
    int i = blockIdx.x * blockDim.x + threadIdx.x;
    if (i >= ETOT) return;
    int d = (i < EE) ? ei[EE + i] : (i - EE);
    atomicAdd(&deg[d], 1);
}
__global__ void k_scan(const int* __restrict__ deg, int* __restrict__ rowptr) {
    __shared__ int sh[512];
    const int VPT = (NN + 511) / 512;
    int t = threadIdx.x;
    int base = t * VPT;
    int sum = 0;
    for (int j = 0; j < VPT; j++) { int i = base + j; if (i < NN) sum += deg[i]; }
    sh[t] = sum;
    __syncthreads();
    for (int off = 1; off < 512; off <<= 1) {
        int v = (t >= off) ? sh[t - off] : 0;
        __syncthreads();
        sh[t] += v;
        __syncthreads();
    }
    int run = (t == 0) ? 0 : sh[t - 1];
    for (int j = 0; j < VPT; j++) {
        int i = base + j;
        if (i < NN) { rowptr[i] = run; run += deg[i]; }
    }
    if (t == 511) rowptr[NN] = sh[511];
}
__global__ void k_scatter(const int* __restrict__ ei, const int* __restrict__ rowptr,
                          int* __restrict__ cnt, int* __restrict__ csr) {
    int i = blockIdx.x * blockDim.x + threadIdx.x;
    if (i >= ETOT) return;
    int s, d;
    if (i < EE) { s = ei[i]; d = ei[EE + i]; }
    else        { s = d = i - EE; }
    int p = rowptr[d] + atomicAdd(&cnt[d], 1);
    csr[p] = s;
}

// ================= split helpers =================
__device__ __forceinline__ void split2(float v, __nv_bfloat16& hi, __nv_bfloat16& lo) {
    hi = __float2bfloat16_rn(v);
    lo = __float2bfloat16_rn(v - __bfloat162float(hi));
}

__global__ void k_split_w(const float* __restrict__ B0, const float* __restrict__ B1,
                          int K, int Nper, int Ntot, __nv_bfloat16* __restrict__ out) {
    int idx = blockIdx.x * blockDim.x + threadIdx.x;
    if (idx >= Ntot * K) return;
    int n = idx / K, k = idx - n * K;
    float v = (n < Nper) ? B0[(size_t)k * Nper + n] : B1[(size_t)k * Nper + (n - Nper)];
    __nv_bfloat16 hi, lo;
    split2(v, hi, lo);
    size_t base = (size_t)n * 3 * K;
    out[base + k] = hi;
    out[base + K + k] = lo;
    out[base + 2 * K + k] = hi;
}

__global__ void k_combined_split(const float* __restrict__ xp, const float* __restrict__ emb,
                                 __nv_bfloat16* __restrict__ chi, __nv_bfloat16* __restrict__ clo) {
    int idx = blockIdx.x * blockDim.x + threadIdx.x;
    if (idx >= NN * KIN) return;
    int i = idx / KIN;
    int k = idx - i * KIN;
    float v;
    if (k < HID) {
        int id = (int)xp[i * (FEAT + 1)];
        v = emb[(size_t)id * HID + k];
    } else {
        v = xp[i * (FEAT + 1) + 1 + (k - HID)];
    }
    __nv_bfloat16 hi, lo;
    split2(v, hi, lo);
    chi[idx] = hi;
    clo[idx] = lo;
}

// ================= HMMA split-bf16 GEMM, cp.async + ldmatrix =================
#define SMP 40   // smem row pitch in bf16 (32 + 8 pad); rows stride 20 words -> conflict-free

template <bool SPLIT_OUT>
__global__ void __launch_bounds__(256) k_gemm_mma(
    const __nv_bfloat16* __restrict__ Ahi, const __nv_bfloat16* __restrict__ Alo,
    const __nv_bfloat16* __restrict__ Bs,
    float* __restrict__ C,
    __nv_bfloat16* __restrict__ Chi, __nv_bfloat16* __restrict__ Clo,
    const float* __restrict__ bias, int relu,
    int M, int Ntot, int K) {
    __shared__ __nv_bfloat16 As[2][128][SMP];
    __shared__ __nv_bfloat16 Bsh[2][128][SMP];

    int tid = threadIdx.x;
    int warp = tid >> 5, lane = tid & 31;
    int warpM = warp >> 1, warpN = warp & 1;     // 4 x 2
    int groupID = lane >> 2, tig = lane & 3;
    int brow = blockIdx.y * 128, bcol = blockIdx.x * 128;

    float acc[2][8][4];
#pragma unroll
    for (int mt = 0; mt < 2; mt++)
#pragma unroll
        for (int nt = 0; nt < 8; nt++)
#pragma unroll
            for (int q = 0; q < 4; q++) acc[mt][nt][q] = 0.f;

    int lrow = tid >> 1;
    int lhalf = tid & 1;

    const int kc = K >> 5;
    const int nc = 3 * kc;
    const int B3K = 3 * K;
    int grA = brow + lrow;
    bool aok = grA < M;
    int asz = aok ? 16 : 0;
    const __nv_bfloat16* arow_safe_hi = Ahi + (size_t)(aok ? grA : 0) * K;
    const __nv_bfloat16* arow_safe_lo = Alo + (size_t)(aok ? grA : 0) * K;
    const __nv_bfloat16* brow_base = Bs + (size_t)(bcol + lrow) * B3K;

    auto issue = [&](int c, int buf) {
        int seg = c / kc;
        int cw = c - seg * kc;
        const __nv_bfloat16* Ap = (seg < 2) ? arow_safe_hi : arow_safe_lo;
        const __nv_bfloat16* ap = Ap + (cw << 5) + lhalf * 16;
        const __nv_bfloat16* bp = brow_base + seg * K + (cw << 5) + lhalf * 16;
        uint32_t ad = smem_u32(&As[buf][lrow][lhalf * 16]);
        uint32_t bd = smem_u32(&Bsh[buf][lrow][lhalf * 16]);
        CP_A16(ad, ap, asz);
        CP_A16(ad + 16, ap + 8, asz);
        CP_A16(bd, bp, 16);
        CP_A16(bd + 16, bp + 8, 16);
    };

    // ldmatrix lane-address precompute
    int a_r  = lane & 15;          // row within 16-row tile
    int a_kh = lane >> 4;          // k-half (0/1)
    int b_j  = lane >> 3;          // matrix index 0..3
    int b_r  = lane & 7;
    int b_nt = b_j >> 1;           // sub col-group (0/1)
    int b_kh = b_j & 1;

    issue(0, 0);
    CP_COMMIT();

    for (int c = 0; c < nc; c++) {
        int buf = c & 1;
        if (c + 1 < nc) {
            issue(c + 1, buf ^ 1);
            CP_COMMIT();
            CP_WAIT1();
        } else {
            CP_WAIT0();
        }
        __syncthreads();

#pragma unroll
        for (int ko = 0; ko < 32; ko += 16) {
            uint32_t af[2][4];
#pragma unroll
            for (int mt = 0; mt < 2; mt++) {
                uint32_t aaddr = smem_u32(&As[buf][warpM * 32 + mt * 16 + a_r][ko + a_kh * 8]);
                ldm_x4(af[mt], aaddr);
            }
            uint32_t bfr[8][2];
#pragma unroll
            for (int ntb = 0; ntb < 8; ntb += 2) {
                uint32_t q[4];
                uint32_t baddr = smem_u32(&Bsh[buf][warpN * 64 + (ntb + b_nt) * 8 + b_r][ko + b_kh * 8]);
                ldm_x4(q, baddr);
                bfr[ntb][0] = q[0]; bfr[ntb][1] = q[1];
                bfr[ntb + 1][0] = q[2]; bfr[ntb + 1][1] = q[3];
            }
#pragma unroll
            for (int mt = 0; mt < 2; mt++)
#pragma unroll
                for (int nt = 0; nt < 8; nt++)
                    mma16816(acc[mt][nt], af[mt], bfr[nt]);
        }
        __syncthreads();
    }

    // epilogue
#pragma unroll
    for (int mt = 0; mt < 2; mt++) {
        int r0 = brow + warpM * 32 + mt * 16 + groupID;
#pragma unroll
        for (int half = 0; half < 2; half++) {
            int r = r0 + half * 8;
            if (r >= M) continue;
#pragma unroll
            for (int nt = 0; nt < 8; nt++) {
                int cn = bcol + warpN * 64 + nt * 8 + 2 * tig;
                float v0 = acc[mt][nt][half * 2];
                float v1 = acc[mt][nt][half * 2 + 1];
                if (!SPLIT_OUT) {
                    *(float2*)(C + (size_t)r * Ntot + cn) = make_float2(v0, v1);
                } else {
                    if (bias) { v0 += bias[cn]; v1 += bias[cn + 1]; }
                    if (relu) { v0 = fmaxf(v0, 0.f); v1 = fmaxf(v1, 0.f); }
                    __nv_bfloat16 h0, l0, h1, l1;
                    split2(v0, h0, l0);
                    split2(v1, h1, l1);
                    size_t o = (size_t)r * Ntot + cn;
                    Chi[o] = h0; Chi[o + 1] = h1;
                    Clo[o] = l0; Clo[o + 1] = l1;
                }
            }
        }
    }
}

// ================= GATv2: warp per (node, head), no barriers =================
// FUSE_OUT (HEADS==1): apply out head [128x10] in-register and write final output.
template <int HEADS, bool RELU, bool SPLIT, bool FUSE_OUT>
__global__ void __launch_bounds__(128) k_gat_warp(
    const float* __restrict__ xl, const float* __restrict__ xr, int xstride,
    const float* __restrict__ att, const float* __restrict__ bias,
    const int* __restrict__ rowptr, const int* __restrict__ csr,
    float* __restrict__ outf,
    __nv_bfloat16* __restrict__ outhi, __nv_bfloat16* __restrict__ outlo,
    const float* __restrict__ outW, const float* __restrict__ outb) {
    int warp = threadIdx.x >> 5, lane = threadIdx.x & 31;
    int gw = blockIdx.x * 4 + warp;
    int node = gw / HEADS;
    int h = gw - node * HEADS;
    if (node >= NN) return;

    int co = h * 128 + lane * 4;
    float4 xr4  = *(const float4*)(xr + (size_t)node * xstride + co);
    float4 att4 = *(const float4*)(att + co);

    float m = -INFINITY, s = 0.f;
    float4 acc = make_float4(0.f, 0.f, 0.f, 0.f);

    int beg = rowptr[node], end = rowptr[node + 1];
    int src_n = csr[beg];
    float4 x_n = *(const float4*)(xl + (size_t)src_n * xstride + co);

    for (int i = beg; i < end; i++) {
        float4 xc = x_n;
        if (i + 1 < end) {
            int sn = csr[i + 1];
            x_n = *(const float4*)(xl + (size_t)sn * xstride + co);
        }
        float v0 = xc.x + xr4.x, v1 = xc.y + xr4.y, v2 = xc.z + xr4.z, v3 = xc.w + xr4.w;
        v0 = (v0 > 0.f) ? v0 : 0.2f * v0;
        v1 = (v1 > 0.f) ? v1 : 0.2f * v1;
        v2 = (v2 > 0.f) ? v2 : 0.2f * v2;
        v3 = (v3 > 0.f) ? v3 : 0.2f * v3;
        float p = v0 * att4.x + v1 * att4.y + v2 * att4.z + v3 * att4.w;
#pragma unroll
        for (int off = 16; off > 0; off >>= 1)
            p += __shfl_xor_sync(0xffffffffu, p, off);
        float e = p;
        float mn = fmaxf(m, e);
        float cs = __expf(m - mn);
        float w  = __expf(e - mn);
        s = s * cs + w;
        acc.x = acc.x * cs + w * xc.x;
        acc.y = acc.y * cs + w * xc.y;
        acc.z = acc.z * cs + w * xc.z;
        acc.w = acc.w * cs + w * xc.w;
        m = mn;
    }

    float inv = 1.f / (s + 1e-16f);
    float4 b4 = *(const float4*)(bias + co);
    float o0 = acc.x * inv + b4.x;
    float o1 = acc.y * inv + b4.y;
    float o2 = acc.z * inv + b4.z;
    float o3 = acc.w * inv + b4.w;
    if (RELU) {
        o0 = fmaxf(o0, 0.f); o1 = fmaxf(o1, 0.f);
        o2 = fmaxf(o2, 0.f); o3 = fmaxf(o3, 0.f);
    }
    if (FUSE_OUT) {
        // out head: x2 row (spread float4/lane) @ W[128x10] + b
        float oacc[OUTD];
#pragma unroll
        for (int j = 0; j < OUTD; j++) oacc[j] = 0.f;
        float ov[4] = {o0, o1, o2, o3};
#pragma unroll
        for (int q = 0; q < 4; q++) {
            int k = lane * 4 + q;
            float x = ov[q];
#pragma unroll
            for (int j = 0; j < OUTD; j++) oacc[j] += x * outW[k * OUTD + j];
        }
#pragma unroll
        for (int j = 0; j < OUTD; j++)
#pragma unroll
            for (int off = 16; off > 0; off >>= 1)
                oacc[j] += __shfl_down_sync(0xffffffffu, oacc[j], off);
        if (lane == 0) {
#pragma unroll
            for (int j = 0; j < OUTD; j++)
                outf[(size_t)node * OUTD + j] = oacc[j] + outb[j];
        }
        return;
    }
    size_t oidx = (size_t)node * (HEADS * 128) + co;
    if (SPLIT) {
        __nv_bfloat16 hh[4], ll[4];
        split2(o0, hh[0], ll[0]);
        split2(o1, hh[1], ll[1]);
        split2(o2, hh[2], ll[2]);
        split2(o3, hh[3], ll[3]);
        *(uint2*)(outhi + oidx) = *(uint2*)hh;
        *(uint2*)(outlo + oidx) = *(uint2*)ll;
    } else {
        *(float4*)(outf + oidx) = make_float4(o0, o1, o2, o3);
    }
}

// ================= launcher =================
extern "C" void kernel_launch(void* const* d_in, const int* in_sizes, int n_in,
                              void* d_out, int out_size) {
    const float* xp     = (const float*)d_in[0];
    const int*   ei     = (const int*)  d_in[1];
    const float* emb    = (const float*)d_in[2];
    const float* proj_W = (const float*)d_in[3];
    const float* proj_b = (const float*)d_in[4];
    const float* W1l    = (const float*)d_in[5];
    const float* W1r    = (const float*)d_in[6];
    const float* att1   = (const float*)d_in[7];
    const float* b1     = (const float*)d_in[8];
    const float* W2l    = (const float*)d_in[9];
    const float* W2r    = (const float*)d_in[10];
    const float* att2   = (const float*)d_in[11];
    const float* b2     = (const float*)d_in[12];
    const float* out_W  = (const float*)d_in[13];
    const float* out_b  = (const float*)d_in[14];
    float* out = (float*)d_out;

    __nv_bfloat16 *combhi, *comblo, *x0hi, *x0lo, *x1hi, *x1lo, *bproj, *bw1, *bw2;
    float *xlr1, *xlr2;
    int *deg, *rowptr, *cnt, *csr;
    cudaGetSymbolAddress((void**)&combhi, g_combhi);
    cudaGetSymbolAddress((void**)&comblo, g_comblo);
    cudaGetSymbolAddress((void**)&x0hi,   g_x0hi);
    cudaGetSymbolAddress((void**)&x0lo,   g_x0lo);
    cudaGetSymbolAddress((void**)&xlr1,   g_xlr1);
    cudaGetSymbolAddress((void**)&x1hi,   g_x1hi);
    cudaGetSymbolAddress((void**)&x1lo,   g_x1lo);
    cudaGetSymbolAddress((void**)&xlr2,   g_xlr2);
    cudaGetSymbolAddress((void**)&bproj,  g_bproj);
    cudaGetSymbolAddress((void**)&bw1,    g_b1);
    cudaGetSymbolAddress((void**)&bw2,    g_b2);
    cudaGetSymbolAddress((void**)&deg,    g_deg);
    cudaGetSymbolAddress((void**)&rowptr, g_rowptr);
    cudaGetSymbolAddress((void**)&cnt,    g_cnt);
    cudaGetSymbolAddress((void**)&csr,    g_csr);

    const int MB = (NN + 127) / 128;   // 157

    // launches 1-5: prep (ordered so launch #6 = k_gemm_mma for ncu -s 5 -c 1)
    k_combined_split<<<(NN * KIN + 255) / 256, 256>>>(xp, emb, combhi, comblo);
    k_split_w<<<(128 * KIN + 255) / 256, 256>>>(proj_W, nullptr, KIN, 128, 128, bproj);
    k_split_w<<<(1024 * HID + 255) / 256, 256>>>(W1l, W1r, HID, 512, 1024, bw1);
    k_split_w<<<(256 * 512 + 255) / 256, 256>>>(W2l, W2r, 512, 128, 256, bw2);
    k_zero_int<<<(NN + 255) / 256, 256>>>(deg, NN);

    // launch 6: proj GEMM (profiled)
    k_gemm_mma<true><<<dim3(1, MB), 256>>>(combhi, comblo, bproj,
                                           nullptr, x0hi, x0lo, proj_b, 1,
                                           NN, 128, KIN);

    // CSR build
    k_hist<<<(ETOT + 255) / 256, 256>>>(ei, deg);
    k_scan<<<1, 512>>>(deg, rowptr);
    k_zero_int<<<(NN + 255) / 256, 256>>>(cnt, NN);
    k_scatter<<<(ETOT + 255) / 256, 256>>>(ei, rowptr, cnt, csr);

    // layer 1
    k_gemm_mma<false><<<dim3(8, MB), 256>>>(x0hi, x0lo, bw1,
                                            xlr1, nullptr, nullptr, nullptr, 0,
                                            NN, 1024, HID);
    k_gat_warp<4, true, true, false><<<NN, 128>>>(xlr1, xlr1 + 512, 1024, att1, b1,
                                                  rowptr, csr, nullptr, x1hi, x1lo,
                                                  nullptr, nullptr);

    // layer 2 + fused output head
    k_gemm_mma<false><<<dim3(2, MB), 256>>>(x1hi, x1lo, bw2,
                                            xlr2, nullptr, nullptr, nullptr, 0,
                                            NN, 256, 512);
    k_gat_warp<1, false, false, true><<<(NN + 3) / 4, 128>>>(xlr2, xlr2 + 128, 256, att2, b2,
                                                             rowptr, csr, out, nullptr, nullptr,
                                                             out_W, out_b);
}

// round 12
// speedup vs baseline: 2.1391x; 1.0287x over previous
#include <cuda_runtime.h>
#include <cuda_bf16.h>
#include <cstdint>
#include <math.h>

#define NN   20000
#define EE   320000
#define ETOT (EE + NN)
#define FEAT 64
#define HID  128
#define OUTD 10
#define KIN  (HID + FEAT)   // 192

// ================= scratch (static device memory) =================
__device__ __nv_bfloat16 g_combhi[NN * KIN];
__device__ __nv_bfloat16 g_comblo[NN * KIN];
__device__ __nv_bfloat16 g_x0hi[NN * HID];
__device__ __nv_bfloat16 g_x0lo[NN * HID];
__device__ float         g_xlr1[NN * 1024];
__device__ __nv_bfloat16 g_x1hi[NN * 512];
__device__ __nv_bfloat16 g_x1lo[NN * 512];
__device__ float         g_xlr2[NN * 256];
__device__ __nv_bfloat16 g_bproj[128 * 3 * KIN];
__device__ __nv_bfloat16 g_b1   [1024 * 3 * HID];
__device__ __nv_bfloat16 g_b2   [256 * 3 * 512];
__device__ int g_deg[NN];
__device__ int g_rowptr[NN + 1];
__device__ int g_cnt[NN];
__device__ int g_csr[ETOT];

// ================= asm helpers =================
__device__ __forceinline__ uint32_t smem_u32(const void* p) {
    return (uint32_t)__cvta_generic_to_shared(p);
}
#define CP_A16(sa, gp, n) asm volatile("cp.async.cg.shared.global [%0], [%1], 16, %2;" :: "r"(sa), "l"(gp), "r"(n))
#define CP_COMMIT()       asm volatile("cp.async.commit_group;")
#define CP_WAIT1()        asm volatile("cp.async.wait_group 1;")
#define CP_WAIT0()        asm volatile("cp.async.wait_group 0;")

__device__ __forceinline__ void ldm_x4(uint32_t* r, uint32_t a) {
    asm volatile("ldmatrix.sync.aligned.m8n8.x4.shared.b16 {%0,%1,%2,%3}, [%4];"
                 : "=r"(r[0]), "=r"(r[1]), "=r"(r[2]), "=r"(r[3]) : "r"(a));
}
__device__ __forceinline__ void mma16816(float* c, const uint32_t* a, const uint32_t* b) {
    asm volatile(
        "mma.sync.aligned.m16n8k16.row.col.f32.bf16.bf16.f32 "
        "{%0,%1,%2,%3}, {%4,%5,%6,%7}, {%8,%9}, {%0,%1,%2,%3};"
        : "+f"(c[0]), "+f"(c[1]), "+f"(c[2]), "+f"(c[3])
        : "r"(a[0]), "r"(a[1]), "r"(a[2]), "r"(a[3]), "r"(b[0]), "r"(b[1]));
}

// ================= CSR build =================
__global__ void k_zero2(int* __restrict__ a, int* __restrict__ b) {
    int i = blockIdx.x * blockDim.x + threadIdx.x;
    if (i < NN) { a[i] = 0; b[i] = 0; }
}
__global__ void k_hist(const int* __restrict__ ei, int* __restrict__ deg) {
    int i = blockIdx.x * blockDim.x + threadIdx.x;
    if (i >= ETOT) return;
    int d = (i < EE) ? ei[EE + i] : (i - EE);
    atomicAdd(&deg[d], 1);
}
__global__ void k_scan(const int* __restrict__ deg, int* __restrict__ rowptr) {
    __shared__ int sh[512];
    const int VPT = (NN + 511) / 512;
    int t = threadIdx.x;
    int base = t * VPT;
    int sum = 0;
    for (int j = 0; j < VPT; j++) { int i = base + j; if (i < NN) sum += deg[i]; }
    sh[t] = sum;
    __syncthreads();
    for (int off = 1; off < 512; off <<= 1) {
        int v = (t >= off) ? sh[t - off] : 0;
        __syncthreads();
        sh[t] += v;
        __syncthreads();
    }
    int run = (t == 0) ? 0 : sh[t - 1];
    for (int j = 0; j < VPT; j++) {
        int i = base + j;
        if (i < NN) { rowptr[i] = run; run += deg[i]; }
    }
    if (t == 511) rowptr[NN] = sh[511];
}
__global__ void k_scatter(const int* __restrict__ ei, const int* __restrict__ rowptr,
                          int* __restrict__ cnt, int* __restrict__ csr) {
    int i = blockIdx.x * blockDim.x + threadIdx.x;
    if (i >= ETOT) return;
    int s, d;
    if (i < EE) { s = ei[i]; d = ei[EE + i]; }
    else        { s = d = i - EE; }
    int p = rowptr[d] + atomicAdd(&cnt[d], 1);
    csr[p] = s;
}

// ================= split helpers =================
__device__ __forceinline__ void split2(float v, __nv_bfloat16& hi, __nv_bfloat16& lo) {
    hi = __float2bfloat16_rn(v);
    lo = __float2bfloat16_rn(v - __bfloat162float(hi));
}

__device__ __forceinline__ void split_one(const float* __restrict__ B0,
                                          const float* __restrict__ B1,
                                          int K, int Nper,
                                          __nv_bfloat16* __restrict__ out, int idx) {
    int n = idx / K, k = idx - n * K;
    float v = (n < Nper) ? B0[(size_t)k * Nper + n] : B1[(size_t)k * Nper + (n - Nper)];
    __nv_bfloat16 hi, lo;
    split2(v, hi, lo);
    size_t base = (size_t)n * 3 * K;
    out[base + k] = hi;
    out[base + K + k] = lo;
    out[base + 2 * K + k] = hi;
}

#define R0 (128 * KIN)
#define R1 (1024 * HID)
#define R2 (256 * 512)
__global__ void k_split_all(const float* __restrict__ proj_W,
                            const float* __restrict__ W1l, const float* __restrict__ W1r,
                            const float* __restrict__ W2l, const float* __restrict__ W2r,
                            __nv_bfloat16* __restrict__ bproj,
                            __nv_bfloat16* __restrict__ bw1,
                            __nv_bfloat16* __restrict__ bw2) {
    int idx = blockIdx.x * blockDim.x + threadIdx.x;
    if (idx < R0) {
        split_one(proj_W, nullptr, KIN, 128, bproj, idx);
    } else if (idx < R0 + R1) {
        split_one(W1l, W1r, HID, 512, bw1, idx - R0);
    } else if (idx < R0 + R1 + R2) {
        split_one(W2l, W2r, 512, 128, bw2, idx - R0 - R1);
    }
}

__global__ void k_combined_split(const float* __restrict__ xp, const float* __restrict__ emb,
                                 __nv_bfloat16* __restrict__ chi, __nv_bfloat16* __restrict__ clo) {
    int idx = blockIdx.x * blockDim.x + threadIdx.x;
    if (idx >= NN * KIN) return;
    int i = idx / KIN;
    int k = idx - i * KIN;
    float v;
    if (k < HID) {
        int id = (int)xp[i * (FEAT + 1)];
        v = emb[(size_t)id * HID + k];
    } else {
        v = xp[i * (FEAT + 1) + 1 + (k - HID)];
    }
    __nv_bfloat16 hi, lo;
    split2(v, hi, lo);
    chi[idx] = hi;
    clo[idx] = lo;
}

// ================= HMMA split-bf16 GEMM: 3-stage cp.async, 1 sync/chunk =================
#define SMP 40   // smem row pitch in bf16 (32 + 8 pad)

template <bool SPLIT_OUT>
__global__ void __launch_bounds__(256) k_gemm_mma(
    const __nv_bfloat16* __restrict__ Ahi, const __nv_bfloat16* __restrict__ Alo,
    const __nv_bfloat16* __restrict__ Bs,
    float* __restrict__ C,
    __nv_bfloat16* __restrict__ Chi, __nv_bfloat16* __restrict__ Clo,
    const float* __restrict__ bias, int relu,
    int M, int Ntot, int K) {
    __shared__ __nv_bfloat16 As[3][128][SMP];
    __shared__ __nv_bfloat16 Bsh[3][128][SMP];

    int tid = threadIdx.x;
    int warp = tid >> 5, lane = tid & 31;
    int warpM = warp >> 1, warpN = warp & 1;     // 4 x 2
    int groupID = lane >> 2, tig = lane & 3;
    int brow = blockIdx.y * 128, bcol = blockIdx.x * 128;

    float acc[2][8][4];
#pragma unroll
    for (int mt = 0; mt < 2; mt++)
#pragma unroll
        for (int nt = 0; nt < 8; nt++)
#pragma unroll
            for (int q = 0; q < 4; q++) acc[mt][nt][q] = 0.f;

    int lrow = tid >> 1;
    int lhalf = tid & 1;

    const int kc = K >> 5;
    const int nc = 3 * kc;
    const int B3K = 3 * K;
    int grA = brow + lrow;
    bool aok = grA < M;
    int asz = aok ? 16 : 0;
    const __nv_bfloat16* arow_safe_hi = Ahi + (size_t)(aok ? grA : 0) * K;
    const __nv_bfloat16* arow_safe_lo = Alo + (size_t)(aok ? grA : 0) * K;
    const __nv_bfloat16* brow_base = Bs + (size_t)(bcol + lrow) * B3K;

    auto issue = [&](int c, int buf) {
        int seg = c / kc;
        int cw = c - seg * kc;
        const __nv_bfloat16* Ap = (seg < 2) ? arow_safe_hi : arow_safe_lo;
        const __nv_bfloat16* ap = Ap + (cw << 5) + lhalf * 16;
        const __nv_bfloat16* bp = brow_base + seg * K + (cw << 5) + lhalf * 16;
        uint32_t ad = smem_u32(&As[buf][lrow][lhalf * 16]);
        uint32_t bd = smem_u32(&Bsh[buf][lrow][lhalf * 16]);
        CP_A16(ad, ap, asz);
        CP_A16(ad + 16, ap + 8, asz);
        CP_A16(bd, bp, 16);
        CP_A16(bd + 16, bp + 8, 16);
    };

    // ldmatrix lane-address precompute
    int a_r  = lane & 15;
    int a_kh = lane >> 4;
    int b_j  = lane >> 3;
    int b_r  = lane & 7;
    int b_nt = b_j >> 1;
    int b_kh = b_j & 1;

    issue(0, 0); CP_COMMIT();
    issue(1, 1); CP_COMMIT();

    int buf = 0;
    for (int c = 0; c < nc; c++) {
        if (c + 1 < nc) CP_WAIT1(); else CP_WAIT0();
        __syncthreads();
        // safe: all warps have finished reading buffer (c-1)%3 == (c+2)%3
        if (c + 2 < nc) {
            issue(c + 2, (buf + 2) % 3);
            CP_COMMIT();
        }

#pragma unroll
        for (int ko = 0; ko < 32; ko += 16) {
            uint32_t af[2][4];
#pragma unroll
            for (int mt = 0; mt < 2; mt++) {
                uint32_t aaddr = smem_u32(&As[buf][warpM * 32 + mt * 16 + a_r][ko + a_kh * 8]);
                ldm_x4(af[mt], aaddr);
            }
            uint32_t bfr[8][2];
#pragma unroll
            for (int ntb = 0; ntb < 8; ntb += 2) {
                uint32_t q[4];
                uint32_t baddr = smem_u32(&Bsh[buf][warpN * 64 + (ntb + b_nt) * 8 + b_r][ko + b_kh * 8]);
                ldm_x4(q, baddr);
                bfr[ntb][0] = q[0]; bfr[ntb][1] = q[1];
                bfr[ntb + 1][0] = q[2]; bfr[ntb + 1][1] = q[3];
            }
#pragma unroll
            for (int mt = 0; mt < 2; mt++)
#pragma unroll
                for (int nt = 0; nt < 8; nt++)
                    mma16816(acc[mt][nt], af[mt], bfr[nt]);
        }
        buf = (buf + 1) % 3;
    }

    // epilogue
#pragma unroll
    for (int mt = 0; mt < 2; mt++) {
        int r0 = brow + warpM * 32 + mt * 16 + groupID;
#pragma unroll
        for (int half = 0; half < 2; half++) {
            int r = r0 + half * 8;
            if (r >= M) continue;
#pragma unroll
            for (int nt = 0; nt < 8; nt++) {
                int cn = bcol + warpN * 64 + nt * 8 + 2 * tig;
                float v0 = acc[mt][nt][half * 2];
                float v1 = acc[mt][nt][half * 2 + 1];
                if (!SPLIT_OUT) {
                    *(float2*)(C + (size_t)r * Ntot + cn) = make_float2(v0, v1);
                } else {
                    if (bias) { v0 += bias[cn]; v1 += bias[cn + 1]; }
                    if (relu) { v0 = fmaxf(v0, 0.f); v1 = fmaxf(v1, 0.f); }
                    __nv_bfloat16 h0, l0, h1, l1;
                    split2(v0, h0, l0);
                    split2(v1, h1, l1);
                    size_t o = (size_t)r * Ntot + cn;
                    Chi[o] = h0; Chi[o + 1] = h1;
                    Clo[o] = l0; Clo[o + 1] = l1;
                }
            }
        }
    }
}

// ================= GATv2: warp per (node, head), 2-deep prefetch =================
template <int HEADS, bool RELU, bool SPLIT, bool FUSE_OUT>
__global__ void __launch_bounds__(128) k_gat_warp(
    const float* __restrict__ xl, const float* __restrict__ xr, int xstride,
    const float* __restrict__ att, const float* __restrict__ bias,
    const int* __restrict__ rowptr, const int* __restrict__ csr,
    float* __restrict__ outf,
    __nv_bfloat16* __restrict__ outhi, __nv_bfloat16* __restrict__ outlo,
    const float* __restrict__ outW, const float* __restrict__ outb) {
    int warp = threadIdx.x >> 5, lane = threadIdx.x & 31;
    int gw = blockIdx.x * 4 + warp;
    int node = gw / HEADS;
    int h = gw - node * HEADS;
    if (node >= NN) return;

    int co = h * 128 + lane * 4;
    float4 xr4  = *(const float4*)(xr + (size_t)node * xstride + co);
    float4 att4 = *(const float4*)(att + co);

    float m = -INFINITY, s = 0.f;
    float4 acc = make_float4(0.f, 0.f, 0.f, 0.f);

    int beg = rowptr[node], end = rowptr[node + 1];
    // 2-deep row prefetch
    int sA = csr[beg];
    float4 xA = *(const float4*)(xl + (size_t)sA * xstride + co);
    float4 xB = xA;
    if (beg + 1 < end) {
        int sB = csr[beg + 1];
        xB = *(const float4*)(xl + (size_t)sB * xstride + co);
    }

    for (int i = beg; i < end; i++) {
        float4 xc = xA;
        xA = xB;
        if (i + 2 < end) {
            int sn = csr[i + 2];
            xB = *(const float4*)(xl + (size_t)sn * xstride + co);
        }
        float v0 = xc.x + xr4.x, v1 = xc.y + xr4.y, v2 = xc.z + xr4.z, v3 = xc.w + xr4.w;
        v0 = (v0 > 0.f) ? v0 : 0.2f * v0;
        v1 = (v1 > 0.f) ? v1 : 0.2f * v1;
        v2 = (v2 > 0.f) ? v2 : 0.2f * v2;
        v3 = (v3 > 0.f) ? v3 : 0.2f * v3;
        float p = v0 * att4.x + v1 * att4.y + v2 * att4.z + v3 * att4.w;
#pragma unroll
        for (int off = 16; off > 0; off >>= 1)
            p += __shfl_xor_sync(0xffffffffu, p, off);
        float e = p;
        float mn = fmaxf(m, e);
        float cs = __expf(m - mn);
        float w  = __expf(e - mn);
        s = s * cs + w;
        acc.x = acc.x * cs + w * xc.x;
        acc.y = acc.y * cs + w * xc.y;
        acc.z = acc.z * cs + w * xc.z;
        acc.w = acc.w * cs + w * xc.w;
        m = mn;
    }

    float inv = 1.f / (s + 1e-16f);
    float4 b4 = *(const float4*)(bias + co);
    float o0 = acc.x * inv + b4.x;
    float o1 = acc.y * inv + b4.y;
    float o2 = acc.z * inv + b4.z;
    float o3 = acc.w * inv + b4.w;
    if (RELU) {
        o0 = fmaxf(o0, 0.f); o1 = fmaxf(o1, 0.f);
        o2 = fmaxf(o2, 0.f); o3 = fmaxf(o3, 0.f);
    }
    if (FUSE_OUT) {
        float oacc[OUTD];
#pragma unroll
        for (int j = 0; j < OUTD; j++) oacc[j] = 0.f;
        float ov[4] = {o0, o1, o2, o3};
#pragma unroll
        for (int q = 0; q < 4; q++) {
            int k = lane * 4 + q;
            float x = ov[q];
#pragma unroll
            for (int j = 0; j < OUTD; j++) oacc[j] += x * outW[k * OUTD + j];
        }
#pragma unroll
        for (int j = 0; j < OUTD; j++)
#pragma unroll
            for (int off = 16; off > 0; off >>= 1)
                oacc[j] += __shfl_down_sync(0xffffffffu, oacc[j], off);
        if (lane == 0) {
#pragma unroll
            for (int j = 0; j < OUTD; j++)
                outf[(size_t)node * OUTD + j] = oacc[j] + outb[j];
        }
        return;
    }
    size_t oidx = (size_t)node * (HEADS * 128) + co;
    if (SPLIT) {
        __nv_bfloat16 hh[4], ll[4];
        split2(o0, hh[0], ll[0]);
        split2(o1, hh[1], ll[1]);
        split2(o2, hh[2], ll[2]);
        split2(o3, hh[3], ll[3]);
        *(uint2*)(outhi + oidx) = *(uint2*)hh;
        *(uint2*)(outlo + oidx) = *(uint2*)ll;
    } else {
        *(float4*)(outf + oidx) = make_float4(o0, o1, o2, o3);
    }
}

// ================= launcher =================
extern "C" void kernel_launch(void* const* d_in, const int* in_sizes, int n_in,
                              void* d_out, int out_size) {
    const float* xp     = (const float*)d_in[0];
    const int*   ei     = (const int*)  d_in[1];
    const float* emb    = (const float*)d_in[2];
    const float* proj_W = (const float*)d_in[3];
    const float* proj_b = (const float*)d_in[4];
    const float* W1l    = (const float*)d_in[5];
    const float* W1r    = (const float*)d_in[6];
    const float* att1   = (const float*)d_in[7];
    const float* b1     = (const float*)d_in[8];
    const float* W2l    = (const float*)d_in[9];
    const float* W2r    = (const float*)d_in[10];
    const float* att2   = (const float*)d_in[11];
    const float* b2     = (const float*)d_in[12];
    const float* out_W  = (const float*)d_in[13];
    const float* out_b  = (const float*)d_in[14];
    float* out = (float*)d_out;

    __nv_bfloat16 *combhi, *comblo, *x0hi, *x0lo, *x1hi, *x1lo, *bproj, *bw1, *bw2;
    float *xlr1, *xlr2;
    int *deg, *rowptr, *cnt, *csr;
    cudaGetSymbolAddress((void**)&combhi, g_combhi);
    cudaGetSymbolAddress((void**)&comblo, g_comblo);
    cudaGetSymbolAddress((void**)&x0hi,   g_x0hi);
    cudaGetSymbolAddress((void**)&x0lo,   g_x0lo);
    cudaGetSymbolAddress((void**)&xlr1,   g_xlr1);
    cudaGetSymbolAddress((void**)&x1hi,   g_x1hi);
    cudaGetSymbolAddress((void**)&x1lo,   g_x1lo);
    cudaGetSymbolAddress((void**)&xlr2,   g_xlr2);
    cudaGetSymbolAddress((void**)&bproj,  g_bproj);
    cudaGetSymbolAddress((void**)&bw1,    g_b1);
    cudaGetSymbolAddress((void**)&bw2,    g_b2);
    cudaGetSymbolAddress((void**)&deg,    g_deg);
    cudaGetSymbolAddress((void**)&rowptr, g_rowptr);
    cudaGetSymbolAddress((void**)&cnt,    g_cnt);
    cudaGetSymbolAddress((void**)&csr,    g_csr);

    const int MB = (NN + 127) / 128;   // 157
    const int SPLIT_TOT = R0 + R1 + R2;

    // launches ordered so my #4 (= 6th overall under ncu -s 5) is the big layer-1 GEMM
    k_combined_split<<<(NN * KIN + 255) / 256, 256>>>(xp, emb, combhi, comblo);
    k_split_all<<<(SPLIT_TOT + 255) / 256, 256>>>(proj_W, W1l, W1r, W2l, W2r,
                                                  bproj, bw1, bw2);
    k_gemm_mma<true><<<dim3(1, MB), 256>>>(combhi, comblo, bproj,
                                           nullptr, x0hi, x0lo, proj_b, 1,
                                           NN, 128, KIN);
    k_gemm_mma<false><<<dim3(8, MB), 256>>>(x0hi, x0lo, bw1,
                                            xlr1, nullptr, nullptr, nullptr, 0,
                                            NN, 1024, HID);

    // CSR build
    k_zero2<<<(NN + 255) / 256, 256>>>(deg, cnt);
    k_hist<<<(ETOT + 255) / 256, 256>>>(ei, deg);
    k_scan<<<1, 512>>>(deg, rowptr);
    k_scatter<<<(ETOT + 255) / 256, 256>>>(ei, rowptr, cnt, csr);

    // layer 1 GAT
    k_gat_warp<4, true, true, false><<<NN, 128>>>(xlr1, xlr1 + 512, 1024, att1, b1,
                                                  rowptr, csr, nullptr, x1hi, x1lo,
                                                  nullptr, nullptr);

    // layer 2 + fused output head
    k_gemm_mma<false><<<dim3(2, MB), 256>>>(x1hi, x1lo, bw2,
                                            xlr2, nullptr, nullptr, nullptr, 0,
                                            NN, 256, 512);
    k_gat_warp<1, false, false, true><<<(NN + 3) / 4, 128>>>(xlr2, xlr2 + 128, 256, att2, b2,
                                                             rowptr, csr, out, nullptr, nullptr,
                                                             out_W, out_b);
}

// round 16
// speedup vs baseline: 2.3835x; 1.1143x over previous
#include <cuda_runtime.h>
#include <cuda_bf16.h>
#include <cstdint>
#include <math.h>

#define NN   20000
#define EE   320000
#define ETOT (EE + NN)
#define FEAT 64
#define HID  128
#define OUTD 10
#define KIN  (HID + FEAT)   // 192

// ================= scratch (static device memory) =================
__device__ __nv_bfloat16 g_combhi[NN * KIN];
__device__ __nv_bfloat16 g_comblo[NN * KIN];
__device__ __nv_bfloat16 g_x0hi[NN * HID];
__device__ __nv_bfloat16 g_x0lo[NN * HID];
__device__ float         g_xlr1[NN * 1024];
__device__ __nv_bfloat16 g_x1hi[NN * 512];
__device__ __nv_bfloat16 g_x1lo[NN * 512];
__device__ float         g_xlr2[NN * 256];
__device__ __nv_bfloat16 g_bproj[128 * 3 * KIN];
__device__ __nv_bfloat16 g_b1   [1024 * 3 * HID];
__device__ __nv_bfloat16 g_b2   [256 * 3 * 512];
__device__ int g_deg[NN];
__device__ int g_rowptr[NN + 1];
__device__ int g_cnt[NN];
__device__ int g_csr[ETOT];

// ================= asm helpers =================
__device__ __forceinline__ uint32_t smem_u32(const void* p) {
    return (uint32_t)__cvta_generic_to_shared(p);
}
#define CP_A16(sa, gp, n) asm volatile("cp.async.cg.shared.global [%0], [%1], 16, %2;" :: "r"(sa), "l"(gp), "r"(n))
#define CP_COMMIT()       asm volatile("cp.async.commit_group;")
#define CP_WAIT1()        asm volatile("cp.async.wait_group 1;")
#define CP_WAIT0()        asm volatile("cp.async.wait_group 0;")

__device__ __forceinline__ void ldm_x4(uint32_t* r, uint32_t a) {
    asm volatile("ldmatrix.sync.aligned.m8n8.x4.shared.b16 {%0,%1,%2,%3}, [%4];"
                 : "=r"(r[0]), "=r"(r[1]), "=r"(r[2]), "=r"(r[3]) : "r"(a));
}
__device__ __forceinline__ void mma16816(float* c, const uint32_t* a, const uint32_t* b) {
    asm volatile(
        "mma.sync.aligned.m16n8k16.row.col.f32.bf16.bf16.f32 "
        "{%0,%1,%2,%3}, {%4,%5,%6,%7}, {%8,%9}, {%0,%1,%2,%3};"
        : "+f"(c[0]), "+f"(c[1]), "+f"(c[2]), "+f"(c[3])
        : "r"(a[0]), "r"(a[1]), "r"(a[2]), "r"(a[3]), "r"(b[0]), "r"(b[1]));
}

// ================= CSR build =================
__global__ void k_zero2(int* __restrict__ a, int* __restrict__ b) {
    int i = blockIdx.x * blockDim.x + threadIdx.x;
    if (i < NN) { a[i] = 0; b[i] = 0; }
}
__global__ void k_hist(const int* __restrict__ ei, int* __restrict__ deg) {
    int i = blockIdx.x * blockDim.x + threadIdx.x;
    if (i >= ETOT) return;
    int d = (i < EE) ? ei[EE + i] : (i - EE);
    atomicAdd(&deg[d], 1);
}
__global__ void k_scan(const int* __restrict__ deg, int* __restrict__ rowptr) {
    __shared__ int sh[512];
    const int VPT = (NN + 511) / 512;
    int t = threadIdx.x;
    int base = t * VPT;
    int sum = 0;
    for (int j = 0; j < VPT; j++) { int i = base + j; if (i < NN) sum += deg[i]; }
    sh[t] = sum;
    __syncthreads();
    for (int off = 1; off < 512; off <<= 1) {
        int v = (t >= off) ? sh[t - off] : 0;
        __syncthreads();
        sh[t] += v;
        __syncthreads();
    }
    int run = (t == 0) ? 0 : sh[t - 1];
    for (int j = 0; j < VPT; j++) {
        int i = base + j;
        if (i < NN) { rowptr[i] = run; run += deg[i]; }
    }
    if (t == 511) rowptr[NN] = sh[511];
}
__global__ void k_scatter(const int* __restrict__ ei, const int* __restrict__ rowptr,
                          int* __restrict__ cnt, int* __restrict__ csr) {
    int i = blockIdx.x * blockDim.x + threadIdx.x;
    if (i >= ETOT) return;
    int s, d;
    if (i < EE) { s = ei[i]; d = ei[EE + i]; }
    else        { s = d = i - EE; }
    int p = rowptr[d] + atomicAdd(&cnt[d], 1);
    csr[p] = s;
}

// ================= split helpers =================
__device__ __forceinline__ void split2(float v, __nv_bfloat16& hi, __nv_bfloat16& lo) {
    hi = __float2bfloat16_rn(v);
    lo = __float2bfloat16_rn(v - __bfloat162float(hi));
}

__device__ __forceinline__ void split_one(const float* __restrict__ B0,
                                          const float* __restrict__ B1,
                                          int K, int Nper,
                                          __nv_bfloat16* __restrict__ out, int idx) {
    int n = idx / K, k = idx - n * K;
    float v = (n < Nper) ? B0[(size_t)k * Nper + n] : B1[(size_t)k * Nper + (n - Nper)];
    __nv_bfloat16 hi, lo;
    split2(v, hi, lo);
    size_t base = (size_t)n * 3 * K;
    out[base + k] = hi;
    out[base + K + k] = lo;
    out[base + 2 * K + k] = hi;
}

#define R0 (128 * KIN)
#define R1 (1024 * HID)
#define R2 (256 * 512)
__global__ void k_split_all(const float* __restrict__ proj_W,
                            const float* __restrict__ W1l, const float* __restrict__ W1r,
                            const float* __restrict__ W2l, const float* __restrict__ W2r,
                            __nv_bfloat16* __restrict__ bproj,
                            __nv_bfloat16* __restrict__ bw1,
                            __nv_bfloat16* __restrict__ bw2) {
    int idx = blockIdx.x * blockDim.x + threadIdx.x;
    if (idx < R0) {
        split_one(proj_W, nullptr, KIN, 128, bproj, idx);
    } else if (idx < R0 + R1) {
        split_one(W1l, W1r, HID, 512, bw1, idx - R0);
    } else if (idx < R0 + R1 + R2) {
        split_one(W2l, W2r, 512, 128, bw2, idx - R0 - R1);
    }
}

__global__ void k_combined_split(const float* __restrict__ xp, const float* __restrict__ emb,
                                 __nv_bfloat16* __restrict__ chi, __nv_bfloat16* __restrict__ clo) {
    int idx = blockIdx.x * blockDim.x + threadIdx.x;
    if (idx >= NN * KIN) return;
    int i = idx / KIN;
    int k = idx - i * KIN;
    float v;
    if (k < HID) {
        int id = (int)xp[i * (FEAT + 1)];
        v = emb[(size_t)id * HID + k];
    } else {
        v = xp[i * (FEAT + 1) + 1 + (k - HID)];
    }
    __nv_bfloat16 hi, lo;
    split2(v, hi, lo);
    chi[idx] = hi;
    clo[idx] = lo;
}

// ================= HMMA split-bf16 GEMM: 128x64 block, 3-stage cp.async =================
// 8 warps (4x2), warp tile 32x32, per-thread acc 2x4x4 = 32 regs -> 4 CTAs/SM.
#define SMP 40   // smem row pitch in bf16 (32 + 8 pad)

template <bool SPLIT_OUT>
__global__ void __launch_bounds__(256, 4) k_gemm_mma(
    const __nv_bfloat16* __restrict__ Ahi, const __nv_bfloat16* __restrict__ Alo,
    const __nv_bfloat16* __restrict__ Bs,
    float* __restrict__ C,
    __nv_bfloat16* __restrict__ Chi, __nv_bfloat16* __restrict__ Clo,
    const float* __restrict__ bias, int relu,
    int M, int Ntot, int K) {
    __shared__ __nv_bfloat16 As[3][128][SMP];
    __shared__ __nv_bfloat16 Bsh[3][64][SMP];

    int tid = threadIdx.x;
    int warp = tid >> 5, lane = tid & 31;
    int warpM = warp >> 1, warpN = warp & 1;     // 4 x 2
    int groupID = lane >> 2, tig = lane & 3;
    int brow = blockIdx.y * 128, bcol = blockIdx.x * 64;

    float acc[2][4][4];
#pragma unroll
    for (int mt = 0; mt < 2; mt++)
#pragma unroll
        for (int nt = 0; nt < 4; nt++)
#pragma unroll
            for (int q = 0; q < 4; q++) acc[mt][nt][q] = 0.f;

    // A loader: 2 threads/row, 16 bf16 (32B) each
    int a_lrow = tid >> 1, a_lhalf = tid & 1;
    // B loader: 4 threads/row, 8 bf16 (16B) each
    int b_lrow = tid >> 2, b_lq = tid & 3;

    const int kc = K >> 5;
    const int nc = 3 * kc;
    const int B3K = 3 * K;
    int grA = brow + a_lrow;
    bool aok = grA < M;
    int asz = aok ? 16 : 0;
    const __nv_bfloat16* arow_safe_hi = Ahi + (size_t)(aok ? grA : 0) * K;
    const __nv_bfloat16* arow_safe_lo = Alo + (size_t)(aok ? grA : 0) * K;
    const __nv_bfloat16* brow_base = Bs + (size_t)(bcol + b_lrow) * B3K;

    auto issue = [&](int c, int buf) {
        int seg = c / kc;
        int cw = c - seg * kc;
        const __nv_bfloat16* Ap = (seg < 2) ? arow_safe_hi : arow_safe_lo;
        const __nv_bfloat16* ap = Ap + (cw << 5) + a_lhalf * 16;
        const __nv_bfloat16* bp = brow_base + seg * K + (cw << 5) + b_lq * 8;
        uint32_t ad = smem_u32(&As[buf][a_lrow][a_lhalf * 16]);
        uint32_t bd = smem_u32(&Bsh[buf][b_lrow][b_lq * 8]);
        CP_A16(ad, ap, asz);
        CP_A16(ad + 16, ap + 8, asz);
        CP_A16(bd, bp, 16);
    };

    // ldmatrix lane-address precompute
    int a_r  = lane & 15;
    int a_kh = lane >> 4;
    int b_j  = lane >> 3;
    int b_r  = lane & 7;
    int b_nt = b_j >> 1;
    int b_kh = b_j & 1;

    issue(0, 0); CP_COMMIT();
    issue(1, 1); CP_COMMIT();

    int buf = 0;
    for (int c = 0; c < nc; c++) {
        if (c + 1 < nc) CP_WAIT1(); else CP_WAIT0();
        __syncthreads();
        if (c + 2 < nc) {
            issue(c + 2, (buf + 2) % 3);
            CP_COMMIT();
        }

#pragma unroll
        for (int ko = 0; ko < 32; ko += 16) {
            uint32_t af[2][4];
#pragma unroll
            for (int mt = 0; mt < 2; mt++) {
                uint32_t aaddr = smem_u32(&As[buf][warpM * 32 + mt * 16 + a_r][ko + a_kh * 8]);
                ldm_x4(af[mt], aaddr);
            }
            uint32_t bfr[4][2];
#pragma unroll
            for (int ntb = 0; ntb < 4; ntb += 2) {
                uint32_t q[4];
                uint32_t baddr = smem_u32(&Bsh[buf][warpN * 32 + (ntb + b_nt) * 8 + b_r][ko + b_kh * 8]);
                ldm_x4(q, baddr);
                bfr[ntb][0] = q[0]; bfr[ntb][1] = q[1];
                bfr[ntb + 1][0] = q[2]; bfr[ntb + 1][1] = q[3];
            }
#pragma unroll
            for (int mt = 0; mt < 2; mt++)
#pragma unroll
                for (int nt = 0; nt < 4; nt++)
                    mma16816(acc[mt][nt], af[mt], bfr[nt]);
        }
        buf = (buf + 1) % 3;
    }

    // epilogue
#pragma unroll
    for (int mt = 0; mt < 2; mt++) {
        int r0 = brow + warpM * 32 + mt * 16 + groupID;
#pragma unroll
        for (int half = 0; half < 2; half++) {
            int r = r0 + half * 8;
            if (r >= M) continue;
#pragma unroll
            for (int nt = 0; nt < 4; nt++) {
                int cn = bcol + warpN * 32 + nt * 8 + 2 * tig;
                float v0 = acc[mt][nt][half * 2];
                float v1 = acc[mt][nt][half * 2 + 1];
                if (!SPLIT_OUT) {
                    *(float2*)(C + (size_t)r * Ntot + cn) = make_float2(v0, v1);
                } else {
                    if (bias) { v0 += bias[cn]; v1 += bias[cn + 1]; }
                    if (relu) { v0 = fmaxf(v0, 0.f); v1 = fmaxf(v1, 0.f); }
                    __nv_bfloat16 h0, l0, h1, l1;
                    split2(v0, h0, l0);
                    split2(v1, h1, l1);
                    size_t o = (size_t)r * Ntot + cn;
                    Chi[o] = h0; Chi[o + 1] = h1;
                    Clo[o] = l0; Clo[o + 1] = l1;
                }
            }
        }
    }
}

// ================= GATv2: warp per (node, head), pairwise edges =================
template <int HEADS, bool RELU, bool SPLIT, bool FUSE_OUT>
__global__ void __launch_bounds__(128) k_gat_warp(
    const float* __restrict__ xl, const float* __restrict__ xr, int xstride,
    const float* __restrict__ att, const float* __restrict__ bias,
    const int* __restrict__ rowptr, const int* __restrict__ csr,
    float* __restrict__ outf,
    __nv_bfloat16* __restrict__ outhi, __nv_bfloat16* __restrict__ outlo,
    const float* __restrict__ outW, const float* __restrict__ outb) {
    int warp = threadIdx.x >> 5, lane = threadIdx.x & 31;
    int gw = blockIdx.x * 4 + warp;
    int node = gw / HEADS;
    int h = gw - node * HEADS;
    if (node >= NN) return;

    int co = h * 128 + lane * 4;
    float4 xr4  = *(const float4*)(xr + (size_t)node * xstride + co);
    float4 att4 = *(const float4*)(att + co);

    float m = -INFINITY, s = 0.f;
    float4 acc = make_float4(0.f, 0.f, 0.f, 0.f);

    int beg = rowptr[node], end = rowptr[node + 1];
    // prefetch first two edges
    float4 xA, xB;
    {
        int sA = csr[beg];
        xA = *(const float4*)(xl + (size_t)sA * xstride + co);
        if (beg + 1 < end) {
            int sB = csr[beg + 1];
            xB = *(const float4*)(xl + (size_t)sB * xstride + co);
        }
    }

    int i = beg;
    for (; i + 1 < end; i += 2) {
        float4 x0 = xA, x1 = xB;
        if (i + 2 < end) {
            int sn = csr[i + 2];
            xA = *(const float4*)(xl + (size_t)sn * xstride + co);
            if (i + 3 < end) {
                int sm2 = csr[i + 3];
                xB = *(const float4*)(xl + (size_t)sm2 * xstride + co);
            }
        }
        // two independent logit chains
        float a0 = x0.x + xr4.x, b0 = x0.y + xr4.y, c0 = x0.z + xr4.z, d0 = x0.w + xr4.w;
        float a1 = x1.x + xr4.x, b1 = x1.y + xr4.y, c1 = x1.z + xr4.z, d1 = x1.w + xr4.w;
        a0 = (a0 > 0.f) ? a0 : 0.2f * a0;  a1 = (a1 > 0.f) ? a1 : 0.2f * a1;
        b0 = (b0 > 0.f) ? b0 : 0.2f * b0;  b1 = (b1 > 0.f) ? b1 : 0.2f * b1;
        c0 = (c0 > 0.f) ? c0 : 0.2f * c0;  c1 = (c1 > 0.f) ? c1 : 0.2f * c1;
        d0 = (d0 > 0.f) ? d0 : 0.2f * d0;  d1 = (d1 > 0.f) ? d1 : 0.2f * d1;
        float p0 = a0 * att4.x + b0 * att4.y + c0 * att4.z + d0 * att4.w;
        float p1 = a1 * att4.x + b1 * att4.y + c1 * att4.z + d1 * att4.w;
#pragma unroll
        for (int off = 16; off > 0; off >>= 1) {
            p0 += __shfl_xor_sync(0xffffffffu, p0, off);
            p1 += __shfl_xor_sync(0xffffffffu, p1, off);
        }
        // pair softmax merge
        float mn2 = fmaxf(p0, p1);
        float w0 = __expf(p0 - mn2);
        float w1 = __expf(p1 - mn2);
        float s2 = w0 + w1;
        float px = w0 * x0.x + w1 * x1.x;
        float py = w0 * x0.y + w1 * x1.y;
        float pz = w0 * x0.z + w1 * x1.z;
        float pw = w0 * x0.w + w1 * x1.w;
        float mn = fmaxf(m, mn2);
        float cs = __expf(m - mn);
        float cw = __expf(mn2 - mn);
        s = s * cs + s2 * cw;
        acc.x = acc.x * cs + px * cw;
        acc.y = acc.y * cs + py * cw;
        acc.z = acc.z * cs + pz * cw;
        acc.w = acc.w * cs + pw * cw;
        m = mn;
    }
    if (i < end) {   // tail single edge
        float4 xc = xA;
        float v0 = xc.x + xr4.x, v1 = xc.y + xr4.y, v2 = xc.z + xr4.z, v3 = xc.w + xr4.w;
        v0 = (v0 > 0.f) ? v0 : 0.2f * v0;
        v1 = (v1 > 0.f) ? v1 : 0.2f * v1;
        v2 = (v2 > 0.f) ? v2 : 0.2f * v2;
        v3 = (v3 > 0.f) ? v3 : 0.2f * v3;
        float p = v0 * att4.x + v1 * att4.y + v2 * att4.z + v3 * att4.w;
#pragma unroll
        for (int off = 16; off > 0; off >>= 1)
            p += __shfl_xor_sync(0xffffffffu, p, off);
        float mn = fmaxf(m, p);
        float cs = __expf(m - mn);
        float w  = __expf(p - mn);
        s = s * cs + w;
        acc.x = acc.x * cs + w * xc.x;
        acc.y = acc.y * cs + w * xc.y;
        acc.z = acc.z * cs + w * xc.z;
        acc.w = acc.w * cs + w * xc.w;
        m = mn;
    }

    float inv = 1.f / (s + 1e-16f);
    float4 b4 = *(const float4*)(bias + co);
    float o0 = acc.x * inv + b4.x;
    float o1 = acc.y * inv + b4.y;
    float o2 = acc.z * inv + b4.z;
    float o3 = acc.w * inv + b4.w;
    if (RELU) {
        o0 = fmaxf(o0, 0.f); o1 = fmaxf(o1, 0.f);
        o2 = fmaxf(o2, 0.f); o3 = fmaxf(o3, 0.f);
    }
    if (FUSE_OUT) {
        float oacc[OUTD];
#pragma unroll
        for (int j = 0; j < OUTD; j++) oacc[j] = 0.f;
        float ov[4] = {o0, o1, o2, o3};
#pragma unroll
        for (int q = 0; q < 4; q++) {
            int k = lane * 4 + q;
            float x = ov[q];
#pragma unroll
            for (int j = 0; j < OUTD; j++) oacc[j] += x * outW[k * OUTD + j];
        }
#pragma unroll
        for (int j = 0; j < OUTD; j++)
#pragma unroll
            for (int off = 16; off > 0; off >>= 1)
                oacc[j] += __shfl_down_sync(0xffffffffu, oacc[j], off);
        if (lane == 0) {
#pragma unroll
            for (int j = 0; j < OUTD; j++)
                outf[(size_t)node * OUTD + j] = oacc[j] + outb[j];
        }
        return;
    }
    size_t oidx = (size_t)node * (HEADS * 128) + co;
    if (SPLIT) {
        __nv_bfloat16 hh[4], ll[4];
        split2(o0, hh[0], ll[0]);
        split2(o1, hh[1], ll[1]);
        split2(o2, hh[2], ll[2]);
        split2(o3, hh[3], ll[3]);
        *(uint2*)(outhi + oidx) = *(uint2*)hh;
        *(uint2*)(outlo + oidx) = *(uint2*)ll;
    } else {
        *(float4*)(outf + oidx) = make_float4(o0, o1, o2, o3);
    }
}

// ================= launcher =================
extern "C" void kernel_launch(void* const* d_in, const int* in_sizes, int n_in,
                              void* d_out, int out_size) {
    const float* xp     = (const float*)d_in[0];
    const int*   ei     = (const int*)  d_in[1];
    const float* emb    = (const float*)d_in[2];
    const float* proj_W = (const float*)d_in[3];
    const float* proj_b = (const float*)d_in[4];
    const float* W1l    = (const float*)d_in[5];
    const float* W1r    = (const float*)d_in[6];
    const float* att1   = (const float*)d_in[7];
    const float* b1     = (const float*)d_in[8];
    const float* W2l    = (const float*)d_in[9];
    const float* W2r    = (const float*)d_in[10];
    const float* att2   = (const float*)d_in[11];
    const float* b2     = (const float*)d_in[12];
    const float* out_W  = (const float*)d_in[13];
    const float* out_b  = (const float*)d_in[14];
    float* out = (float*)d_out;

    __nv_bfloat16 *combhi, *comblo, *x0hi, *x0lo, *x1hi, *x1lo, *bproj, *bw1, *bw2;
    float *xlr1, *xlr2;
    int *deg, *rowptr, *cnt, *csr;
    cudaGetSymbolAddress((void**)&combhi, g_combhi);
    cudaGetSymbolAddress((void**)&comblo, g_comblo);
    cudaGetSymbolAddress((void**)&x0hi,   g_x0hi);
    cudaGetSymbolAddress((void**)&x0lo,   g_x0lo);
    cudaGetSymbolAddress((void**)&xlr1,   g_xlr1);
    cudaGetSymbolAddress((void**)&x1hi,   g_x1hi);
    cudaGetSymbolAddress((void**)&x1lo,   g_x1lo);
    cudaGetSymbolAddress((void**)&xlr2,   g_xlr2);
    cudaGetSymbolAddress((void**)&bproj,  g_bproj);
    cudaGetSymbolAddress((void**)&bw1,    g_b1);
    cudaGetSymbolAddress((void**)&bw2,    g_b2);
    cudaGetSymbolAddress((void**)&deg,    g_deg);
    cudaGetSymbolAddress((void**)&rowptr, g_rowptr);
    cudaGetSymbolAddress((void**)&cnt,    g_cnt);
    cudaGetSymbolAddress((void**)&csr,    g_csr);

    const int MB = (NN + 127) / 128;   // 157
    const int SPLIT_TOT = R0 + R1 + R2;

    // launches ordered so my #4 (6th overall under ncu -s 5) is the big layer-1 GEMM
    k_combined_split<<<(NN * KIN + 255) / 256, 256>>>(xp, emb, combhi, comblo);
    k_split_all<<<(SPLIT_TOT + 255) / 256, 256>>>(proj_W, W1l, W1r, W2l, W2r,
                                                  bproj, bw1, bw2);
    k_gemm_mma<true><<<dim3(2, MB), 256>>>(combhi, comblo, bproj,
                                           nullptr, x0hi, x0lo, proj_b, 1,
                                           NN, 128, KIN);
    k_gemm_mma<false><<<dim3(16, MB), 256>>>(x0hi, x0lo, bw1,
                                             xlr1, nullptr, nullptr, nullptr, 0,
                                             NN, 1024, HID);

    // CSR build
    k_zero2<<<(NN + 255) / 256, 256>>>(deg, cnt);
    k_hist<<<(ETOT + 255) / 256, 256>>>(ei, deg);
    k_scan<<<1, 512>>>(deg, rowptr);
    k_scatter<<<(ETOT + 255) / 256, 256>>>(ei, rowptr, cnt, csr);

    // layer 1 GAT
    k_gat_warp<4, true, true, false><<<NN, 128>>>(xlr1, xlr1 + 512, 1024, att1, b1,
                                                  rowptr, csr, nullptr, x1hi, x1lo,
                                                  nullptr, nullptr);

    // layer 2 + fused output head
    k_gemm_mma<false><<<dim3(4, MB), 256>>>(x1hi, x1lo, bw2,
                                            xlr2, nullptr, nullptr, nullptr, 0,
                                            NN, 256, 512);
    k_gat_warp<1, false, false, true><<<(NN + 3) / 4, 128>>>(xlr2, xlr2 + 128, 256, att2, b2,
                                                             rowptr, csr, out, nullptr, nullptr,
                                                             out_W, out_b);
}